// round 6
// baseline (speedup 1.0000x reference)
#include <cuda_runtime.h>
#include <cuda_bf16.h>
#include <math.h>
#include <mma.h>

using namespace nvcuda;

#define D   128
#define CH  7
#define NC  8
#define NS  4
#define MAXM  40000
#define MP    (MAXM + 128)   // padded rows so full-tile wmma stores stay in bounds
#define MAXET 680000

// ---------------- scratch (static device globals; no allocation) -------------
__device__ int   g_count[MAXM + 1];
__device__ int   g_off[MAXM + 1];
__device__ int   g_cursor[MAXM];
__device__ int   g_csr[MAXET];
__device__ float g_xlA[(size_t)MP * D];
__device__ float g_xrA[(size_t)MP * D];
__device__ float g_xlC[(size_t)MP * D];
__device__ float g_xrC[(size_t)MP * D];
__device__ float g_hA [(size_t)MP * D];
__device__ float g_hC [(size_t)MP * D];
__device__ float g_s1[MP * CH];
__device__ float g_s2[MP * CH];
__device__ float g_lg[64 * CH];

// ---------------- CSR build --------------------------------------------------
__global__ void k_hist(const int* __restrict__ tgt, int E, int M) {
    int stride = gridDim.x * blockDim.x;
    int ET = E + M;
    for (int i = blockIdx.x * blockDim.x + threadIdx.x; i < ET; i += stride) {
        int t = (i < E) ? tgt[i] : (i - E);
        atomicAdd(&g_count[t], 1);
    }
}

__global__ void k_scan(int M) {  // single block, 1024 threads
    __shared__ int sh[1024];
    int tid = threadIdx.x;
    int chunk = (M + 1023) >> 10;
    int beg = tid * chunk;
    int end = min(beg + chunk, M);
    int s = 0;
    for (int i = beg; i < end; i++) s += g_count[i];
    sh[tid] = s;
    __syncthreads();
    for (int o = 1; o < 1024; o <<= 1) {
        int v = (tid >= o) ? sh[tid - o] : 0;
        __syncthreads();
        sh[tid] += v;
        __syncthreads();
    }
    int run = sh[tid] - s;
    for (int i = beg; i < end; i++) {
        g_off[i] = run;
        g_cursor[i] = run;
        run += g_count[i];
    }
    if (tid == 1023) g_off[M] = sh[1023];
}

__global__ void k_scatter(const int* __restrict__ src, const int* __restrict__ tgt,
                          int E, int M) {
    int stride = gridDim.x * blockDim.x;
    int ET = E + M;
    for (int i = blockIdx.x * blockDim.x + threadIdx.x; i < ET; i += stride) {
        int t, s;
        if (i < E) { t = tgt[i]; s = src[i]; }
        else       { t = i - E;  s = i - E; }
        int pos = atomicAdd(&g_cursor[t], 1);
        g_csr[pos] = s;
    }
}

// sort each segment ascending in shared memory -> deterministic CSR order
#define SORT_NODES 128
#define SORT_CAP   6144
__global__ void k_sortseg2(int M) {
    __shared__ int sh[SORT_CAP];
    int n0 = blockIdx.x * SORT_NODES;
    if (n0 >= M) return;
    int nEnd = min(n0 + SORT_NODES, M);
    int beg = g_off[n0], end = g_off[nEnd];
    int span = end - beg;
    int tid = threadIdx.x;  // 128
    if (span <= SORT_CAP) {
        for (int i = beg + tid; i < end; i += blockDim.x) sh[i - beg] = g_csr[i];
        __syncthreads();
        int node = n0 + tid;
        if (node < M) {
            int s = g_off[node] - beg, e = g_off[node + 1] - beg;
            for (int i = s + 1; i < e; i++) {
                int v = sh[i]; int j = i - 1;
                while (j >= s && sh[j] > v) { sh[j + 1] = sh[j]; j--; }
                sh[j + 1] = v;
            }
        }
        __syncthreads();
        for (int i = beg + tid; i < end; i += blockDim.x) g_csr[i] = sh[i - beg];
    } else {
        int node = n0 + tid;
        if (node < M) {
            int s = g_off[node], e = g_off[node + 1];
            for (int i = s + 1; i < e; i++) {
                int v = g_csr[i]; int j = i - 1;
                while (j >= s && g_csr[j] > v) { g_csr[j + 1] = g_csr[j]; j--; }
                g_csr[j + 1] = v;
            }
        }
    }
}

// ---------------- bf16x3 tensor-core multi-GEMM ------------------------------
// C[p] = A @ W[p] for p < npass (NO bias — folded into downstream gat kernels).
// A split once into bf16 hi/lo in smem; per pass: W split, pure HMMA, direct
// global store from accumulator fragments.
#define LDB 136  // bf16 leading dim (128 + 8 pad)

__device__ __forceinline__ void split_store4(float4 v, __nv_bfloat16* hi,
                                             __nv_bfloat16* lo, int idx) {
    __nv_bfloat16 h0 = __float2bfloat16(v.x), h1 = __float2bfloat16(v.y),
                  h2 = __float2bfloat16(v.z), h3 = __float2bfloat16(v.w);
    float l0 = v.x - __bfloat162float(h0), l1 = v.y - __bfloat162float(h1),
          l2 = v.z - __bfloat162float(h2), l3 = v.w - __bfloat162float(h3);
    __nv_bfloat162 hp0 = __halves2bfloat162(h0, h1), hp1 = __halves2bfloat162(h2, h3);
    uint2 hv; hv.x = *(unsigned*)&hp0; hv.y = *(unsigned*)&hp1;
    *(uint2*)&hi[idx] = hv;
    __nv_bfloat162 lp0 = __floats2bfloat162_rn(l0, l1), lp1 = __floats2bfloat162_rn(l2, l3);
    uint2 lv; lv.x = *(unsigned*)&lp0; lv.y = *(unsigned*)&lp1;
    *(uint2*)&lo[idx] = lv;
}

__global__ void k_gemmN(const float* __restrict__ A,
                        const float* __restrict__ W0, const float* __restrict__ W1,
                        const float* __restrict__ W2, const float* __restrict__ W3,
                        float* __restrict__ C0, float* __restrict__ C1,
                        float* __restrict__ C2, float* __restrict__ C3,
                        int M, int npass) {
    extern __shared__ char smraw[];
    __nv_bfloat16* Ahi = (__nv_bfloat16*)smraw;
    __nv_bfloat16* Alo = Ahi + 128 * LDB;
    __nv_bfloat16* Whi = Alo + 128 * LDB;
    __nv_bfloat16* Wlo = Whi + 128 * LDB;

    int tid = threadIdx.x;       // 256
    int row0 = blockIdx.x * 128;
    int r = tid >> 1, half = tid & 1;
    int cbase = half * 64;

    // ---- fill A hi/lo (once) ----
    {
        int row = row0 + r;
        const float* ap = A + (size_t)row * D + cbase;
        #pragma unroll
        for (int q = 0; q < 16; q++) {
            float4 v = (row < M) ? *(const float4*)(ap + q * 4)
                                 : make_float4(0.f, 0.f, 0.f, 0.f);
            split_store4(v, Ahi, Alo, r * LDB + cbase + q * 4);
        }
    }

    int w  = tid >> 5;
    int wr = w >> 2, wc = w & 3;   // warp tile: 64 rows x 32 cols

    const float* Wt[4] = {W0, W1, W2, W3};
    float*       Ct[4] = {C0, C1, C2, C3};

    for (int pass = 0; pass < npass; pass++) {
        const float* W = Wt[pass];
        float* C       = Ct[pass];

        if (pass > 0) __syncthreads();   // prior pass done reading W
        {
            const float* wp = W + r * D + cbase;
            #pragma unroll
            for (int q = 0; q < 16; q++)
                split_store4(*(const float4*)(wp + q * 4), Whi, Wlo,
                             r * LDB + cbase + q * 4);
        }
        __syncthreads();

        wmma::fragment<wmma::accumulator, 16, 16, 16, float> acc[4][2];
        #pragma unroll
        for (int m = 0; m < 4; m++)
            #pragma unroll
            for (int n = 0; n < 2; n++) wmma::fill_fragment(acc[m][n], 0.f);

        wmma::fragment<wmma::matrix_a, 16, 16, 16, __nv_bfloat16, wmma::row_major> ah[4], al[4];
        wmma::fragment<wmma::matrix_b, 16, 16, 16, __nv_bfloat16, wmma::row_major> bh[2], bl[2];

        #pragma unroll
        for (int kk = 0; kk < 8; kk++) {
            int k0 = kk * 16;
            #pragma unroll
            for (int n = 0; n < 2; n++) {
                wmma::load_matrix_sync(bh[n], &Whi[k0 * LDB + wc * 32 + n * 16], LDB);
                wmma::load_matrix_sync(bl[n], &Wlo[k0 * LDB + wc * 32 + n * 16], LDB);
            }
            #pragma unroll
            for (int m = 0; m < 4; m++) {
                wmma::load_matrix_sync(ah[m], &Ahi[(wr * 64 + m * 16) * LDB + k0], LDB);
                wmma::load_matrix_sync(al[m], &Alo[(wr * 64 + m * 16) * LDB + k0], LDB);
            }
            #pragma unroll
            for (int m = 0; m < 4; m++)
                #pragma unroll
                for (int n = 0; n < 2; n++) {
                    wmma::mma_sync(acc[m][n], ah[m], bl[n], acc[m][n]);
                    wmma::mma_sync(acc[m][n], al[m], bh[n], acc[m][n]);
                    wmma::mma_sync(acc[m][n], ah[m], bh[n], acc[m][n]);
                }
        }

        // direct store to (row-padded) global
        #pragma unroll
        for (int m = 0; m < 4; m++)
            #pragma unroll
            for (int n = 0; n < 2; n++)
                wmma::store_matrix_sync(
                    C + (size_t)(row0 + wr * 64 + m * 16) * D + wc * 32 + n * 16,
                    acc[m][n], D, wmma::mem_row_major);
    }
}

// ---------------- GATv2 aggregate, Dout=128 ----------------------------------
// 4 edges per iteration, 8 lanes per edge (lane = eg*8 + cg, 16 ch per lane).
// Biases folded: score uses xr + (bl+br); output adds (bl + layer_b).
// Dual-layer: blockIdx.y selects actor(a1) / critic(c1) pointer set.
__global__ void k_gat2(
    const float* __restrict__ xlA, const float* __restrict__ xrA,
    const float* __restrict__ attA, const float* __restrict__ blA,
    const float* __restrict__ brA, const float* __restrict__ boA,
    float* __restrict__ outA,
    const float* __restrict__ xlC, const float* __restrict__ xrC,
    const float* __restrict__ attC, const float* __restrict__ blC,
    const float* __restrict__ brC, const float* __restrict__ boC,
    float* __restrict__ outC,
    int M, float slope) {
    int w = (blockIdx.x * blockDim.x + threadIdx.x) >> 5;
    if (w >= M) return;
    const float *xl, *xr, *att, *bl, *br, *bo; float* out;
    if (blockIdx.y == 0) { xl = xlA; xr = xrA; att = attA; bl = blA; br = brA; bo = boA; out = outA; }
    else                 { xl = xlC; xr = xrC; att = attC; bl = blC; br = brC; bo = boC; out = outC; }
    int lane = threadIdx.x & 31;
    int eg = lane >> 3, cg = lane & 7, cb = cg * 16;

    float xrv[16], attv[16];
    #pragma unroll
    for (int q = 0; q < 4; q++) {
        float4 v  = *(const float4*)(xr + (size_t)w * D + cb + q * 4);
        float4 b1 = *(const float4*)(bl + cb + q * 4);
        float4 b2 = *(const float4*)(br + cb + q * 4);
        xrv[q*4+0] = v.x + b1.x + b2.x; xrv[q*4+1] = v.y + b1.y + b2.y;
        xrv[q*4+2] = v.z + b1.z + b2.z; xrv[q*4+3] = v.w + b1.w + b2.w;
        float4 av = *(const float4*)(att + cb + q * 4);
        attv[q*4+0] = av.x; attv[q*4+1] = av.y; attv[q*4+2] = av.z; attv[q*4+3] = av.w;
    }

    int beg = g_off[w], end = g_off[w + 1];
    float m = -INFINITY, dloc = 0.f;
    float acc[16];
    #pragma unroll
    for (int k = 0; k < 16; k++) acc[k] = 0.f;

    for (int e0 = beg; e0 < end; e0 += 4) {
        int e = e0 + eg;
        bool valid = (e < end);
        int s = g_csr[valid ? e : beg];
        float a[16];
        const float* ap = xl + (size_t)s * D + cb;
        #pragma unroll
        for (int q = 0; q < 4; q++) {
            float4 v = *(const float4*)(ap + q * 4);
            a[q*4+0] = v.x; a[q*4+1] = v.y; a[q*4+2] = v.z; a[q*4+3] = v.w;
        }
        float p = 0.f;
        #pragma unroll
        for (int k = 0; k < 16; k++) {
            float t = a[k] + xrv[k];
            t = (t > 0.f) ? t : 0.2f * t;
            p = fmaf(t, attv[k], p);
        }
        p += __shfl_xor_sync(0xffffffffu, p, 1);
        p += __shfl_xor_sync(0xffffffffu, p, 2);
        p += __shfl_xor_sync(0xffffffffu, p, 4);
        if (!valid) p = -INFINITY;
        float pm = fmaxf(p, __shfl_xor_sync(0xffffffffu, p, 8));
        pm = fmaxf(pm, __shfl_xor_sync(0xffffffffu, pm, 16));
        if (pm > m) {
            float c1 = __expf(m - pm);  // first iter: exp(-inf)=0
            dloc *= c1;
            #pragma unroll
            for (int k = 0; k < 16; k++) acc[k] *= c1;
            m = pm;
        }
        float we = __expf(p - m);       // 0 for invalid lanes
        dloc += we;
        #pragma unroll
        for (int k = 0; k < 16; k++) acc[k] = fmaf(we, a[k], acc[k]);
    }

    // merge edge groups
    dloc += __shfl_xor_sync(0xffffffffu, dloc, 8);
    dloc += __shfl_xor_sync(0xffffffffu, dloc, 16);
    #pragma unroll
    for (int k = 0; k < 16; k++) {
        acc[k] += __shfl_xor_sync(0xffffffffu, acc[k], 8);
        acc[k] += __shfl_xor_sync(0xffffffffu, acc[k], 16);
    }
    float inv = 1.f / (dloc + 1e-16f);
    if (eg == 0) {
        #pragma unroll
        for (int q = 0; q < 4; q++) {
            float4 b1 = *(const float4*)(bl + cb + q * 4);
            float4 bb = *(const float4*)(bo + cb + q * 4);
            float o0 = acc[q*4+0] * inv + b1.x + bb.x;
            float o1 = acc[q*4+1] * inv + b1.y + bb.y;
            float o2 = acc[q*4+2] * inv + b1.z + bb.z;
            float o3 = acc[q*4+3] * inv + b1.w + bb.w;
            o0 = (o0 > 0.f) ? o0 : slope * o0;
            o1 = (o1 > 0.f) ? o1 : slope * o1;
            o2 = (o2 > 0.f) ? o2 : slope * o2;
            o3 = (o3 > 0.f) ? o3 : slope * o3;
            *(float4*)(out + (size_t)w * D + cb + q * 4) = make_float4(o0, o1, o2, o3);
        }
    }
}

// ---------------- c2 GATv2 + fused value head --------------------------------
__global__ void k_gatV(
    const float* __restrict__ xl, const float* __restrict__ xr,
    const float* __restrict__ att, const float* __restrict__ bl,
    const float* __restrict__ br, const float* __restrict__ bo,
    const float* __restrict__ fcW, const float* __restrict__ fcb,
    float* __restrict__ value, int M) {
    int w = (blockIdx.x * blockDim.x + threadIdx.x) >> 5;
    if (w >= M) return;
    int lane = threadIdx.x & 31;
    int eg = lane >> 3, cg = lane & 7, cb = cg * 16;

    float xrv[16], attv[16];
    #pragma unroll
    for (int q = 0; q < 4; q++) {
        float4 v  = *(const float4*)(xr + (size_t)w * D + cb + q * 4);
        float4 b1 = *(const float4*)(bl + cb + q * 4);
        float4 b2 = *(const float4*)(br + cb + q * 4);
        xrv[q*4+0] = v.x + b1.x + b2.x; xrv[q*4+1] = v.y + b1.y + b2.y;
        xrv[q*4+2] = v.z + b1.z + b2.z; xrv[q*4+3] = v.w + b1.w + b2.w;
        float4 av = *(const float4*)(att + cb + q * 4);
        attv[q*4+0] = av.x; attv[q*4+1] = av.y; attv[q*4+2] = av.z; attv[q*4+3] = av.w;
    }

    int beg = g_off[w], end = g_off[w + 1];
    float m = -INFINITY, dloc = 0.f;
    float acc[16];
    #pragma unroll
    for (int k = 0; k < 16; k++) acc[k] = 0.f;

    for (int e0 = beg; e0 < end; e0 += 4) {
        int e = e0 + eg;
        bool valid = (e < end);
        int s = g_csr[valid ? e : beg];
        float a[16];
        const float* ap = xl + (size_t)s * D + cb;
        #pragma unroll
        for (int q = 0; q < 4; q++) {
            float4 v = *(const float4*)(ap + q * 4);
            a[q*4+0] = v.x; a[q*4+1] = v.y; a[q*4+2] = v.z; a[q*4+3] = v.w;
        }
        float p = 0.f;
        #pragma unroll
        for (int k = 0; k < 16; k++) {
            float t = a[k] + xrv[k];
            t = (t > 0.f) ? t : 0.2f * t;
            p = fmaf(t, attv[k], p);
        }
        p += __shfl_xor_sync(0xffffffffu, p, 1);
        p += __shfl_xor_sync(0xffffffffu, p, 2);
        p += __shfl_xor_sync(0xffffffffu, p, 4);
        if (!valid) p = -INFINITY;
        float pm = fmaxf(p, __shfl_xor_sync(0xffffffffu, p, 8));
        pm = fmaxf(pm, __shfl_xor_sync(0xffffffffu, pm, 16));
        if (pm > m) {
            float c1 = __expf(m - pm);
            dloc *= c1;
            #pragma unroll
            for (int k = 0; k < 16; k++) acc[k] *= c1;
            m = pm;
        }
        float we = __expf(p - m);
        dloc += we;
        #pragma unroll
        for (int k = 0; k < 16; k++) acc[k] = fmaf(we, a[k], acc[k]);
    }

    dloc += __shfl_xor_sync(0xffffffffu, dloc, 8);
    dloc += __shfl_xor_sync(0xffffffffu, dloc, 16);
    #pragma unroll
    for (int k = 0; k < 16; k++) {
        acc[k] += __shfl_xor_sync(0xffffffffu, acc[k], 8);
        acc[k] += __shfl_xor_sync(0xffffffffu, acc[k], 16);
    }
    float inv = 1.f / (dloc + 1e-16f);

    // value = (gatout + bl + bo) . fcW + fcb
    float v = 0.f;
    #pragma unroll
    for (int q = 0; q < 4; q++) {
        float4 b1 = *(const float4*)(bl + cb + q * 4);
        float4 bb = *(const float4*)(bo + cb + q * 4);
        float4 fw = *(const float4*)(fcW + cb + q * 4);
        v = fmaf(acc[q*4+0] * inv + b1.x + bb.x, fw.x, v);
        v = fmaf(acc[q*4+1] * inv + b1.y + bb.y, fw.y, v);
        v = fmaf(acc[q*4+2] * inv + b1.z + bb.z, fw.z, v);
        v = fmaf(acc[q*4+3] * inv + b1.w + bb.w, fw.w, v);
    }
    v += __shfl_xor_sync(0xffffffffu, v, 1);
    v += __shfl_xor_sync(0xffffffffu, v, 2);
    v += __shfl_xor_sync(0xffffffffu, v, 4);
    if (lane == 0) value[w] = v + fcb[0];
}

// ---------------- GATv2 Dout=7 on ONLY the 32 actor-relevant targets ---------
__global__ void k_gat7s(const float* __restrict__ s1, const float* __restrict__ s2,
                        const float* __restrict__ att, const float* __restrict__ bias,
                        float* __restrict__ lg, int B, int N) {
    int wid = threadIdx.x >> 5;  // 1 block, 32 warps
    if (wid >= B * NC) return;
    int lane = threadIdx.x & 31;
    int row = (wid >> 3) * N + (wid & 7);

    float xrv = (lane < CH) ? s2[row * CH + lane] : 0.f;
    float atv = (lane < CH) ? att[lane] : 0.f;
    int beg = g_off[row], end = g_off[row + 1];

    float m = -INFINITY, d = 0.f, acc = 0.f;
    for (int e = beg; e < end; e++) {
        int s = g_csr[e];
        float av = (lane < CH) ? s1[s * CH + lane] : 0.f;
        float t = av + xrv; t = (t > 0.f) ? t : 0.2f * t;
        float p = t * atv;
        #pragma unroll
        for (int o = 16; o; o >>= 1) p += __shfl_xor_sync(0xffffffffu, p, o);
        if (p <= m) {
            float wgt = __expf(p - m);
            d += wgt; acc += wgt * av;
        } else {
            float c1 = __expf(m - p);
            d = d * c1 + 1.f;
            acc = acc * c1 + av;
            m = p;
        }
    }
    if (lane < CH)
        lg[wid * CH + lane] = acc / (d + 1e-16f) + bias[lane];
}

// ---------------- fused dual GEMM: [M,128]@[128,7]x2, smem-staged ------------
__global__ void k_gemm7x2(const float* __restrict__ A,
                          const float* __restrict__ W1, const float* __restrict__ b1,
                          const float* __restrict__ W2, const float* __restrict__ b2,
                          float* __restrict__ C1, float* __restrict__ C2, int M) {
    __shared__ float As[32][132];
    __shared__ float W1s[D * CH], W2s[D * CH];
    __shared__ float b1s[CH], b2s[CH];
    int tid = threadIdx.x;  // 256
    int row0 = blockIdx.x * 32;

    for (int i = tid; i < D * CH; i += 256) { W1s[i] = W1[i]; W2s[i] = W2[i]; }
    if (tid < CH) { b1s[tid] = b1[tid]; b2s[tid] = b2[tid]; }
    {
        int r = tid >> 3, seg = tid & 7;
        int row = row0 + r;
        const float* ap = A + (size_t)row * D + seg * 16;
        #pragma unroll
        for (int q = 0; q < 4; q++) {
            float4 v = (row < M) ? *(const float4*)(ap + q * 4)
                                 : make_float4(0.f, 0.f, 0.f, 0.f);
            *(float4*)&As[r][seg * 16 + q * 4] = v;
        }
    }
    __syncthreads();

    int r = tid >> 3, c = tid & 7;
    int row = row0 + r;
    if (row < M && c < CH) {
        float s1 = 0.f, s2 = 0.f;
        #pragma unroll 16
        for (int k = 0; k < D; k++) {
            float a = As[r][k];
            s1 += a * W1s[k * CH + c];
            s2 += a * W2s[k * CH + c];
        }
        C1[row * CH + c] = s1 + b1s[c];
        C2[row * CH + c] = s2 + b2s[c];
    }
}

// ---------------- actor head: softmax + gumbel + top-4 + sel -----------------
__global__ void k_actor(const float* __restrict__ logits, const float* __restrict__ gu,
                        float* __restrict__ out, int B, int N) {
    __shared__ float shp[4][NC][CH];
    int tid = threadIdx.x;            // 32 threads
    int b = tid >> 3, i = tid & 7;
    bool active = tid < B * NC;
    if (active) {
        float l[CH], mx = -INFINITY;
        for (int c = 0; c < CH; c++) { l[c] = logits[tid * CH + c]; mx = fmaxf(mx, l[c]); }
        float s = 0.f;
        for (int c = 0; c < CH; c++) { l[c] = expf(l[c] - mx); s += l[c]; }
        for (int c = 0; c < CH; c++) shp[b][i][c] = l[c] / s;
    }
    __syncthreads();
    if (active) {
        float sc[CH];
        for (int c = 0; c < CH; c++) {
            float u = gu[(b * NC + i) * CH + c];
            float g = -logf(-logf(u));
            sc[c] = logf(shp[b][i][c]) + g;
        }
        int base = (b * NC + i) * NS;
        int seloff = B * NC * NS;
        for (int j = 0; j < NS; j++) {
            int best = 0; float bv = -INFINITY;
            for (int c = 0; c < CH; c++)
                if (sc[c] > bv) { bv = sc[c]; best = c; }
            out[base + j] = (float)best;
            out[seloff + base + j] = shp[b][best][j];
            sc[best] = -INFINITY;
        }
    }
}

// ---------------- launch -----------------------------------------------------
extern "C" void kernel_launch(void* const* d_in, const int* in_sizes, int n_in,
                              void* d_out, int out_size) {
    const float* x  = (const float*)d_in[0];
    const int*   ei = (const int*)d_in[1];
    const float* gu = (const float*)d_in[2];
    const float* Wp[4][6];
    for (int l = 0; l < 4; l++)
        for (int j = 0; j < 6; j++)
            Wp[l][j] = (const float*)d_in[3 + l * 6 + j];
    const float* fcW = (const float*)d_in[27];
    const float* fcb = (const float*)d_in[28];

    int M = in_sizes[0] / D;
    int E = in_sizes[1] / 2;
    int B = in_sizes[2] / (NC * CH);
    int N = M / B;
    int ET = E + M;
    float* out = (float*)d_out;

    void *pc, *pxlA, *pxrA, *pxlC, *pxrC, *phA, *phC, *ps1, *ps2, *plg;
    cudaGetSymbolAddress(&pc,   g_count);
    cudaGetSymbolAddress(&pxlA, g_xlA);
    cudaGetSymbolAddress(&pxrA, g_xrA);
    cudaGetSymbolAddress(&pxlC, g_xlC);
    cudaGetSymbolAddress(&pxrC, g_xrC);
    cudaGetSymbolAddress(&phA,  g_hA);
    cudaGetSymbolAddress(&phC,  g_hC);
    cudaGetSymbolAddress(&ps1,  g_s1);
    cudaGetSymbolAddress(&ps2,  g_s2);
    cudaGetSymbolAddress(&plg,  g_lg);
    float* xlA = (float*)pxlA; float* xrA = (float*)pxrA;
    float* xlC = (float*)pxlC; float* xrC = (float*)pxrC;
    float* hA  = (float*)phA;  float* hC  = (float*)phC;
    float* s1  = (float*)ps1;  float* s2  = (float*)ps2;
    float* lg  = (float*)plg;

    const int tb = 256;
    // ---- CSR build (shared by all GAT layers) ----
    cudaMemsetAsync(pc, 0, (size_t)(M + 1) * sizeof(int));
    int gE = (ET + tb - 1) / tb; if (gE > 4096) gE = 4096;
    k_hist<<<gE, tb>>>(ei + E, E, M);
    k_scan<<<1, 1024>>>(M);
    k_scatter<<<gE, tb>>>(ei, ei + E, E, M);
    k_sortseg2<<<(M + SORT_NODES - 1) / SORT_NODES, SORT_NODES>>>(M);

    // ---- GEMM config ----
    size_t smemN = (size_t)4 * 128 * LDB * sizeof(__nv_bfloat16);  // 139264
    cudaFuncSetAttribute(k_gemmN, cudaFuncAttributeMaxDynamicSharedMemorySize, (int)smemN);
    int gg  = (M + 127) / 128;
    int gwB = (M * 32 + tb - 1) / tb;
    int g32 = (M + 31) / 32;

    // ---- layer 1 (actor a1 + critic c1): 4 projections in one launch ----
    k_gemmN<<<gg, tb, smemN>>>(x, Wp[0][0], Wp[0][2], Wp[2][0], Wp[2][2],
                               xlA, xrA, xlC, xrC, M, 4);
    k_gat2<<<dim3(gwB, 2), tb>>>(xlA, xrA, Wp[0][4], Wp[0][1], Wp[0][3], Wp[0][5], hA,
                                 xlC, xrC, Wp[2][4], Wp[2][1], Wp[2][3], Wp[2][5], hC,
                                 M, 0.01f);

    // ---- actor head ----
    k_gemm7x2<<<g32, tb>>>(hA, Wp[1][0], Wp[1][1], Wp[1][2], Wp[1][3], s1, s2, M);
    k_gat7s<<<1, 1024>>>(s1, s2, Wp[1][4], Wp[1][5], lg, B, N);
    k_actor<<<1, 32>>>(lg, gu, out, B, N);

    // ---- critic layer 2 + value (fused) ----
    k_gemmN<<<gg, tb, smemN>>>(hC, Wp[3][0], Wp[3][2], Wp[3][0], Wp[3][2],
                               xlA, xrA, xlA, xrA, M, 2);
    k_gatV<<<gwB, tb>>>(xlA, xrA, Wp[3][4], Wp[3][1], Wp[3][3], Wp[3][5],
                        fcW, fcb, out + 2 * B * NC * NS, M);
}

// round 8
// speedup vs baseline: 1.2100x; 1.2100x over previous
#include <cuda_runtime.h>
#include <cuda_bf16.h>
#include <math.h>
#include <mma.h>

using namespace nvcuda;

#define D   128
#define CH  7
#define NC  8
#define NS  4
#define MAXM  40000
#define MP    (MAXM + 128)
#define MAXET 680000

// ---------------- scratch (static device globals; no allocation) -------------
__device__ int   g_count[MAXM + 1];
__device__ int   g_off[MAXM + 1];
__device__ int   g_cursor[MAXM];
__device__ int   g_csr[MAXET];
__device__ float g_xlA[(size_t)MP * D];
__device__ float g_xrA[(size_t)MP * D];
__device__ float g_xlC[(size_t)MP * D];
__device__ float g_xrC[(size_t)MP * D];
__device__ float g_hA [(size_t)MP * D];
__device__ float g_hC [(size_t)MP * D];
__device__ float g_s1[MP * CH];
__device__ float g_s2[MP * CH];
__device__ float g_lg[64 * CH];

// ---------------- CSR build --------------------------------------------------
__global__ void k_hist(const int* __restrict__ tgt, int E, int M) {
    int stride = gridDim.x * blockDim.x;
    int ET = E + M;
    for (int i = blockIdx.x * blockDim.x + threadIdx.x; i < ET; i += stride) {
        int t = (i < E) ? tgt[i] : (i - E);
        atomicAdd(&g_count[t], 1);
    }
}

__global__ void k_scan(int M) {  // single block, 1024 threads
    __shared__ int sh[1024];
    int tid = threadIdx.x;
    int chunk = (M + 1023) >> 10;
    int beg = tid * chunk;
    int end = min(beg + chunk, M);
    int s = 0;
    for (int i = beg; i < end; i++) s += g_count[i];
    sh[tid] = s;
    __syncthreads();
    for (int o = 1; o < 1024; o <<= 1) {
        int v = (tid >= o) ? sh[tid - o] : 0;
        __syncthreads();
        sh[tid] += v;
        __syncthreads();
    }
    int run = sh[tid] - s;
    for (int i = beg; i < end; i++) {
        g_off[i] = run;
        g_cursor[i] = run;
        run += g_count[i];
    }
    if (tid == 1023) g_off[M] = sh[1023];
}

__global__ void k_scatter(const int* __restrict__ src, const int* __restrict__ tgt,
                          int E, int M) {
    int stride = gridDim.x * blockDim.x;
    int ET = E + M;
    for (int i = blockIdx.x * blockDim.x + threadIdx.x; i < ET; i += stride) {
        int t, s;
        if (i < E) { t = tgt[i]; s = src[i]; }
        else       { t = i - E;  s = i - E; }
        int pos = atomicAdd(&g_cursor[t], 1);
        g_csr[pos] = s;
    }
}

// sort each segment ascending in shared memory -> deterministic CSR order
#define SORT_NODES 128
#define SORT_CAP   6144
__global__ void k_sortseg2(int M) {
    __shared__ int sh[SORT_CAP];
    int n0 = blockIdx.x * SORT_NODES;
    if (n0 >= M) return;
    int nEnd = min(n0 + SORT_NODES, M);
    int beg = g_off[n0], end = g_off[nEnd];
    int span = end - beg;
    int tid = threadIdx.x;  // 128
    if (span <= SORT_CAP) {
        for (int i = beg + tid; i < end; i += blockDim.x) sh[i - beg] = g_csr[i];
        __syncthreads();
        int node = n0 + tid;
        if (node < M) {
            int s = g_off[node] - beg, e = g_off[node + 1] - beg;
            for (int i = s + 1; i < e; i++) {
                int v = sh[i]; int j = i - 1;
                while (j >= s && sh[j] > v) { sh[j + 1] = sh[j]; j--; }
                sh[j + 1] = v;
            }
        }
        __syncthreads();
        for (int i = beg + tid; i < end; i += blockDim.x) g_csr[i] = sh[i - beg];
    } else {
        int node = n0 + tid;
        if (node < M) {
            int s = g_off[node], e = g_off[node + 1];
            for (int i = s + 1; i < e; i++) {
                int v = g_csr[i]; int j = i - 1;
                while (j >= s && g_csr[j] > v) { g_csr[j + 1] = g_csr[j]; j--; }
                g_csr[j + 1] = v;
            }
        }
    }
}

// ---------------- bf16x3 tensor-core multi-GEMM ------------------------------
// C[p] = A @ W[p] + b[p] for p < npass.  A split ONCE into bf16 hi/lo in smem;
// per pass: W split, pure HMMA mainloop, STAGED smem writeback (R5-proven).
#define LDB 136
#define LDC 132

__device__ __forceinline__ void split_store4(float4 v, __nv_bfloat16* hi,
                                             __nv_bfloat16* lo, int idx) {
    __nv_bfloat16 h0 = __float2bfloat16(v.x), h1 = __float2bfloat16(v.y),
                  h2 = __float2bfloat16(v.z), h3 = __float2bfloat16(v.w);
    float l0 = v.x - __bfloat162float(h0), l1 = v.y - __bfloat162float(h1),
          l2 = v.z - __bfloat162float(h2), l3 = v.w - __bfloat162float(h3);
    __nv_bfloat162 hp0 = __halves2bfloat162(h0, h1), hp1 = __halves2bfloat162(h2, h3);
    uint2 hv; hv.x = *(unsigned*)&hp0; hv.y = *(unsigned*)&hp1;
    *(uint2*)&hi[idx] = hv;
    __nv_bfloat162 lp0 = __floats2bfloat162_rn(l0, l1), lp1 = __floats2bfloat162_rn(l2, l3);
    uint2 lv; lv.x = *(unsigned*)&lp0; lv.y = *(unsigned*)&lp1;
    *(uint2*)&lo[idx] = lv;
}

__global__ void k_gemmN(const float* __restrict__ A,
                        const float* __restrict__ W0, const float* __restrict__ b0,
                        float* __restrict__ C0,
                        const float* __restrict__ W1, const float* __restrict__ b1,
                        float* __restrict__ C1,
                        const float* __restrict__ W2, const float* __restrict__ b2,
                        float* __restrict__ C2,
                        const float* __restrict__ W3, const float* __restrict__ b3,
                        float* __restrict__ C3,
                        int M, int npass) {
    extern __shared__ char smraw[];
    __nv_bfloat16* Ahi = (__nv_bfloat16*)smraw;
    __nv_bfloat16* Alo = Ahi + 128 * LDB;
    __nv_bfloat16* Whi = Alo + 128 * LDB;
    __nv_bfloat16* Wlo = Whi + 128 * LDB;
    float* Cs = (float*)Whi;  // overlay: 128*132*4 = 67584 <= 69632
    __shared__ float bsm[4][128];

    int tid = threadIdx.x;       // 256
    int row0 = blockIdx.x * 128;
    int r = tid >> 1, half = tid & 1;
    int cbase = half * 64;

    const float* Wt[4] = {W0, W1, W2, W3};
    const float* bt[4] = {b0, b1, b2, b3};
    float*       Ct[4] = {C0, C1, C2, C3};
    if (tid < 128)
        for (int p = 0; p < npass; p++) bsm[p][tid] = bt[p][tid];

    // ---- fill A hi/lo (once) ----
    {
        int row = row0 + r;
        const float* ap = A + (size_t)row * D + cbase;
        #pragma unroll
        for (int q = 0; q < 16; q++) {
            float4 v = (row < M) ? *(const float4*)(ap + q * 4)
                                 : make_float4(0.f, 0.f, 0.f, 0.f);
            split_store4(v, Ahi, Alo, r * LDB + cbase + q * 4);
        }
    }

    int w  = tid >> 5;
    int wr = w >> 2, wc = w & 3;   // warp tile: 64 rows x 32 cols

    for (int pass = 0; pass < npass; pass++) {
        const float* W = Wt[pass];
        float* C       = Ct[pass];

        if (pass > 0) __syncthreads();   // prior pass done reading Cs (over W region)
        {
            const float* wp = W + r * D + cbase;
            #pragma unroll
            for (int q = 0; q < 16; q++)
                split_store4(*(const float4*)(wp + q * 4), Whi, Wlo,
                             r * LDB + cbase + q * 4);
        }
        __syncthreads();

        wmma::fragment<wmma::accumulator, 16, 16, 16, float> acc[4][2];
        #pragma unroll
        for (int m = 0; m < 4; m++)
            #pragma unroll
            for (int n = 0; n < 2; n++) wmma::fill_fragment(acc[m][n], 0.f);

        wmma::fragment<wmma::matrix_a, 16, 16, 16, __nv_bfloat16, wmma::row_major> ah[4], al[4];
        wmma::fragment<wmma::matrix_b, 16, 16, 16, __nv_bfloat16, wmma::row_major> bh[2], bl[2];

        #pragma unroll
        for (int kk = 0; kk < 8; kk++) {
            int k0 = kk * 16;
            #pragma unroll
            for (int n = 0; n < 2; n++) {
                wmma::load_matrix_sync(bh[n], &Whi[k0 * LDB + wc * 32 + n * 16], LDB);
                wmma::load_matrix_sync(bl[n], &Wlo[k0 * LDB + wc * 32 + n * 16], LDB);
            }
            #pragma unroll
            for (int m = 0; m < 4; m++) {
                wmma::load_matrix_sync(ah[m], &Ahi[(wr * 64 + m * 16) * LDB + k0], LDB);
                wmma::load_matrix_sync(al[m], &Alo[(wr * 64 + m * 16) * LDB + k0], LDB);
            }
            #pragma unroll
            for (int m = 0; m < 4; m++)
                #pragma unroll
                for (int n = 0; n < 2; n++) {
                    wmma::mma_sync(acc[m][n], ah[m], bl[n], acc[m][n]);
                    wmma::mma_sync(acc[m][n], al[m], bh[n], acc[m][n]);
                    wmma::mma_sync(acc[m][n], ah[m], bh[n], acc[m][n]);
                }
        }
        __syncthreads();  // done reading Whi/Wlo -> overlay Cs

        #pragma unroll
        for (int m = 0; m < 4; m++)
            #pragma unroll
            for (int n = 0; n < 2; n++)
                wmma::store_matrix_sync(&Cs[(wr * 64 + m * 16) * LDC + wc * 32 + n * 16],
                                        acc[m][n], LDC, wmma::mem_row_major);
        __syncthreads();

        {
            int row = row0 + r;
            if (row < M) {
                #pragma unroll
                for (int q = 0; q < 16; q++) {
                    int c = cbase + q * 4;
                    float4 v = *(float4*)&Cs[r * LDC + c];
                    v.x += bsm[pass][c]; v.y += bsm[pass][c + 1];
                    v.z += bsm[pass][c + 2]; v.w += bsm[pass][c + 3];
                    *(float4*)&C[(size_t)row * D + c] = v;
                }
            }
        }
    }
}

// ---------------- GATv2 aggregate, Dout=128 (R5 formulation) -----------------
// one warp per target node, lane = 4 channels, warp-uniform online softmax.
// blockIdx.y selects actor/critic pointer set.
__global__ void k_gat128d(
    const float* __restrict__ xlA, const float* __restrict__ xrA,
    const float* __restrict__ attA, const float* __restrict__ biasA,
    float* __restrict__ outA,
    const float* __restrict__ xlC, const float* __restrict__ xrC,
    const float* __restrict__ attC, const float* __restrict__ biasC,
    float* __restrict__ outC,
    int M, float slope) {
    int w = (blockIdx.x * blockDim.x + threadIdx.x) >> 5;
    if (w >= M) return;
    const float *xl, *xr, *att, *bias; float* out;
    if (blockIdx.y == 0) { xl = xlA; xr = xrA; att = attA; bias = biasA; out = outA; }
    else                 { xl = xlC; xr = xrC; att = attC; bias = biasC; out = outC; }
    int lane = threadIdx.x & 31;

    float4 xr4 = *(const float4*)(xr + (size_t)w * D + lane * 4);
    float4 at4 = *(const float4*)(att + lane * 4);
    int beg = g_off[w], end = g_off[w + 1];

    float m = -INFINITY, d = 0.f;
    float4 acc = make_float4(0.f, 0.f, 0.f, 0.f);

    for (int e = beg; e < end; e++) {
        int s = g_csr[e];
        float4 a = *(const float4*)(xl + (size_t)s * D + lane * 4);
        float t0 = a.x + xr4.x; t0 = (t0 > 0.f) ? t0 : 0.2f * t0;
        float t1 = a.y + xr4.y; t1 = (t1 > 0.f) ? t1 : 0.2f * t1;
        float t2 = a.z + xr4.z; t2 = (t2 > 0.f) ? t2 : 0.2f * t2;
        float t3 = a.w + xr4.w; t3 = (t3 > 0.f) ? t3 : 0.2f * t3;
        float p = t0 * at4.x + t1 * at4.y + t2 * at4.z + t3 * at4.w;
        #pragma unroll
        for (int o = 16; o; o >>= 1) p += __shfl_xor_sync(0xffffffffu, p, o);

        if (p <= m) {
            float wgt = __expf(p - m);
            d += wgt;
            acc.x += wgt * a.x; acc.y += wgt * a.y;
            acc.z += wgt * a.z; acc.w += wgt * a.w;
        } else {
            float c1 = __expf(m - p);
            d = d * c1 + 1.f;
            acc.x = acc.x * c1 + a.x; acc.y = acc.y * c1 + a.y;
            acc.z = acc.z * c1 + a.z; acc.w = acc.w * c1 + a.w;
            m = p;
        }
    }

    float inv = 1.f / (d + 1e-16f);
    float4 b4 = *(const float4*)(bias + lane * 4);
    float o0 = acc.x * inv + b4.x;
    float o1 = acc.y * inv + b4.y;
    float o2 = acc.z * inv + b4.z;
    float o3 = acc.w * inv + b4.w;
    o0 = (o0 > 0.f) ? o0 : slope * o0;
    o1 = (o1 > 0.f) ? o1 : slope * o1;
    o2 = (o2 > 0.f) ? o2 : slope * o2;
    o3 = (o3 > 0.f) ? o3 : slope * o3;
    *(float4*)(out + (size_t)w * D + lane * 4) = make_float4(o0, o1, o2, o3);
}

// ---------------- c2 GATv2 + fused value head (R5 body + dot epilogue) -------
__global__ void k_gatV(
    const float* __restrict__ xl, const float* __restrict__ xr,
    const float* __restrict__ att, const float* __restrict__ bias,
    const float* __restrict__ fcW, const float* __restrict__ fcb,
    float* __restrict__ value, int M) {
    int w = (blockIdx.x * blockDim.x + threadIdx.x) >> 5;
    if (w >= M) return;
    int lane = threadIdx.x & 31;

    float4 xr4 = *(const float4*)(xr + (size_t)w * D + lane * 4);
    float4 at4 = *(const float4*)(att + lane * 4);
    int beg = g_off[w], end = g_off[w + 1];

    float m = -INFINITY, d = 0.f;
    float4 acc = make_float4(0.f, 0.f, 0.f, 0.f);

    for (int e = beg; e < end; e++) {
        int s = g_csr[e];
        float4 a = *(const float4*)(xl + (size_t)s * D + lane * 4);
        float t0 = a.x + xr4.x; t0 = (t0 > 0.f) ? t0 : 0.2f * t0;
        float t1 = a.y + xr4.y; t1 = (t1 > 0.f) ? t1 : 0.2f * t1;
        float t2 = a.z + xr4.z; t2 = (t2 > 0.f) ? t2 : 0.2f * t2;
        float t3 = a.w + xr4.w; t3 = (t3 > 0.f) ? t3 : 0.2f * t3;
        float p = t0 * at4.x + t1 * at4.y + t2 * at4.z + t3 * at4.w;
        #pragma unroll
        for (int o = 16; o; o >>= 1) p += __shfl_xor_sync(0xffffffffu, p, o);

        if (p <= m) {
            float wgt = __expf(p - m);
            d += wgt;
            acc.x += wgt * a.x; acc.y += wgt * a.y;
            acc.z += wgt * a.z; acc.w += wgt * a.w;
        } else {
            float c1 = __expf(m - p);
            d = d * c1 + 1.f;
            acc.x = acc.x * c1 + a.x; acc.y = acc.y * c1 + a.y;
            acc.z = acc.z * c1 + a.z; acc.w = acc.w * c1 + a.w;
            m = p;
        }
    }

    float inv = 1.f / (d + 1e-16f);
    float4 b4 = *(const float4*)(bias + lane * 4);
    float4 fw = *(const float4*)(fcW + lane * 4);
    float v = (acc.x * inv + b4.x) * fw.x
            + (acc.y * inv + b4.y) * fw.y
            + (acc.z * inv + b4.z) * fw.z
            + (acc.w * inv + b4.w) * fw.w;
    #pragma unroll
    for (int o = 16; o; o >>= 1) v += __shfl_xor_sync(0xffffffffu, v, o);
    if (lane == 0) value[w] = v + fcb[0];
}

// ---------------- GATv2 Dout=7 on ONLY the 32 actor-relevant targets ---------
__global__ void k_gat7s(const float* __restrict__ s1, const float* __restrict__ s2,
                        const float* __restrict__ att, const float* __restrict__ bias,
                        float* __restrict__ lg, int B, int N) {
    int wid = threadIdx.x >> 5;  // 1 block, 32 warps
    if (wid >= B * NC) return;
    int lane = threadIdx.x & 31;
    int row = (wid >> 3) * N + (wid & 7);

    float xrv = (lane < CH) ? s2[row * CH + lane] : 0.f;
    float atv = (lane < CH) ? att[lane] : 0.f;
    int beg = g_off[row], end = g_off[row + 1];

    float m = -INFINITY, d = 0.f, acc = 0.f;
    for (int e = beg; e < end; e++) {
        int s = g_csr[e];
        float av = (lane < CH) ? s1[s * CH + lane] : 0.f;
        float t = av + xrv; t = (t > 0.f) ? t : 0.2f * t;
        float p = t * atv;
        #pragma unroll
        for (int o = 16; o; o >>= 1) p += __shfl_xor_sync(0xffffffffu, p, o);
        if (p <= m) {
            float wgt = __expf(p - m);
            d += wgt; acc += wgt * av;
        } else {
            float c1 = __expf(m - p);
            d = d * c1 + 1.f;
            acc = acc * c1 + av;
            m = p;
        }
    }
    if (lane < CH)
        lg[wid * CH + lane] = acc / (d + 1e-16f) + bias[lane];
}

// ---------------- fused dual GEMM: [M,128]@[128,7]x2, smem-staged ------------
__global__ void k_gemm7x2(const float* __restrict__ A,
                          const float* __restrict__ W1, const float* __restrict__ b1,
                          const float* __restrict__ W2, const float* __restrict__ b2,
                          float* __restrict__ C1, float* __restrict__ C2, int M) {
    __shared__ float As[32][132];
    __shared__ float W1s[D * CH], W2s[D * CH];
    __shared__ float b1s[CH], b2s[CH];
    int tid = threadIdx.x;  // 256
    int row0 = blockIdx.x * 32;

    for (int i = tid; i < D * CH; i += 256) { W1s[i] = W1[i]; W2s[i] = W2[i]; }
    if (tid < CH) { b1s[tid] = b1[tid]; b2s[tid] = b2[tid]; }
    {
        int r = tid >> 3, seg = tid & 7;
        int row = row0 + r;
        const float* ap = A + (size_t)row * D + seg * 16;
        #pragma unroll
        for (int q = 0; q < 4; q++) {
            float4 v = (row < M) ? *(const float4*)(ap + q * 4)
                                 : make_float4(0.f, 0.f, 0.f, 0.f);
            *(float4*)&As[r][seg * 16 + q * 4] = v;
        }
    }
    __syncthreads();

    int r = tid >> 3, c = tid & 7;
    int row = row0 + r;
    if (row < M && c < CH) {
        float s1 = 0.f, s2 = 0.f;
        #pragma unroll 16
        for (int k = 0; k < D; k++) {
            float a = As[r][k];
            s1 += a * W1s[k * CH + c];
            s2 += a * W2s[k * CH + c];
        }
        C1[row * CH + c] = s1 + b1s[c];
        C2[row * CH + c] = s2 + b2s[c];
    }
}

// ---------------- actor head: softmax + gumbel + top-4 + sel -----------------
__global__ void k_actor(const float* __restrict__ logits, const float* __restrict__ gu,
                        float* __restrict__ out, int B, int N) {
    __shared__ float shp[4][NC][CH];
    int tid = threadIdx.x;            // 32 threads
    int b = tid >> 3, i = tid & 7;
    bool active = tid < B * NC;
    if (active) {
        float l[CH], mx = -INFINITY;
        for (int c = 0; c < CH; c++) { l[c] = logits[tid * CH + c]; mx = fmaxf(mx, l[c]); }
        float s = 0.f;
        for (int c = 0; c < CH; c++) { l[c] = expf(l[c] - mx); s += l[c]; }
        for (int c = 0; c < CH; c++) shp[b][i][c] = l[c] / s;
    }
    __syncthreads();
    if (active) {
        float sc[CH];
        for (int c = 0; c < CH; c++) {
            float u = gu[(b * NC + i) * CH + c];
            float g = -logf(-logf(u));
            sc[c] = logf(shp[b][i][c]) + g;
        }
        int base = (b * NC + i) * NS;
        int seloff = B * NC * NS;
        for (int j = 0; j < NS; j++) {
            int best = 0; float bv = -INFINITY;
            for (int c = 0; c < CH; c++)
                if (sc[c] > bv) { bv = sc[c]; best = c; }
            out[base + j] = (float)best;
            out[seloff + base + j] = shp[b][best][j];
            sc[best] = -INFINITY;
        }
    }
}

// ---------------- launch -----------------------------------------------------
extern "C" void kernel_launch(void* const* d_in, const int* in_sizes, int n_in,
                              void* d_out, int out_size) {
    const float* x  = (const float*)d_in[0];
    const int*   ei = (const int*)d_in[1];
    const float* gu = (const float*)d_in[2];
    const float* Wp[4][6];
    for (int l = 0; l < 4; l++)
        for (int j = 0; j < 6; j++)
            Wp[l][j] = (const float*)d_in[3 + l * 6 + j];
    const float* fcW = (const float*)d_in[27];
    const float* fcb = (const float*)d_in[28];

    int M = in_sizes[0] / D;
    int E = in_sizes[1] / 2;
    int B = in_sizes[2] / (NC * CH);
    int N = M / B;
    int ET = E + M;
    float* out = (float*)d_out;

    void *pc, *pxlA, *pxrA, *pxlC, *pxrC, *phA, *phC, *ps1, *ps2, *plg;
    cudaGetSymbolAddress(&pc,   g_count);
    cudaGetSymbolAddress(&pxlA, g_xlA);
    cudaGetSymbolAddress(&pxrA, g_xrA);
    cudaGetSymbolAddress(&pxlC, g_xlC);
    cudaGetSymbolAddress(&pxrC, g_xrC);
    cudaGetSymbolAddress(&phA,  g_hA);
    cudaGetSymbolAddress(&phC,  g_hC);
    cudaGetSymbolAddress(&ps1,  g_s1);
    cudaGetSymbolAddress(&ps2,  g_s2);
    cudaGetSymbolAddress(&plg,  g_lg);
    float* xlA = (float*)pxlA; float* xrA = (float*)pxrA;
    float* xlC = (float*)pxlC; float* xrC = (float*)pxrC;
    float* hA  = (float*)phA;  float* hC  = (float*)phC;
    float* s1  = (float*)ps1;  float* s2  = (float*)ps2;
    float* lg  = (float*)plg;

    const int tb = 256;
    // ---- CSR build (shared by all GAT layers) ----
    cudaMemsetAsync(pc, 0, (size_t)(M + 1) * sizeof(int));
    int gE = (ET + tb - 1) / tb; if (gE > 4096) gE = 4096;
    k_hist<<<gE, tb>>>(ei + E, E, M);
    k_scan<<<1, 1024>>>(M);
    k_scatter<<<gE, tb>>>(ei, ei + E, E, M);
    k_sortseg2<<<(M + SORT_NODES - 1) / SORT_NODES, SORT_NODES>>>(M);

    // ---- GEMM config ----
    size_t smemN = (size_t)4 * 128 * LDB * sizeof(__nv_bfloat16);  // 139264
    cudaFuncSetAttribute(k_gemmN, cudaFuncAttributeMaxDynamicSharedMemorySize, (int)smemN);
    int gg  = (M + 127) / 128;
    int gwB = (M * 32 + tb - 1) / tb;
    int g32 = (M + 31) / 32;

    // ---- layer 1 (actor a1 + critic c1): 4 projections, A split once ----
    k_gemmN<<<gg, tb, smemN>>>(x,
                               Wp[0][0], Wp[0][1], xlA,
                               Wp[0][2], Wp[0][3], xrA,
                               Wp[2][0], Wp[2][1], xlC,
                               Wp[2][2], Wp[2][3], xrC, M, 4);
    k_gat128d<<<dim3(gwB, 2), tb>>>(xlA, xrA, Wp[0][4], Wp[0][5], hA,
                                    xlC, xrC, Wp[2][4], Wp[2][5], hC,
                                    M, 0.01f);

    // ---- actor head ----
    k_gemm7x2<<<g32, tb>>>(hA, Wp[1][0], Wp[1][1], Wp[1][2], Wp[1][3], s1, s2, M);
    k_gat7s<<<1, 1024>>>(s1, s2, Wp[1][4], Wp[1][5], lg, B, N);
    k_actor<<<1, 32>>>(lg, gu, out, B, N);

    // ---- critic layer 2 + value (fused) ----
    k_gemmN<<<gg, tb, smemN>>>(hC,
                               Wp[3][0], Wp[3][1], xlA,
                               Wp[3][2], Wp[3][3], xrA,
                               Wp[3][0], Wp[3][1], xlA,
                               Wp[3][2], Wp[3][3], xrA, M, 2);
    k_gatV<<<gwB, tb>>>(xlA, xrA, Wp[3][4], Wp[3][5],
                        fcW, fcb, out + 2 * B * NC * NS, M);
}

// round 9
// speedup vs baseline: 1.3009x; 1.0751x over previous
#include <cuda_runtime.h>
#include <cuda_bf16.h>
#include <math.h>
#include <mma.h>

using namespace nvcuda;

#define D   128
#define CH  7
#define NC  8
#define NS  4
#define MAXM  40000
#define MP    (MAXM + 128)
#define MAXET 680000

// ---------------- scratch (static device globals; no allocation) -------------
__device__ int   g_count[MAXM + 1];
__device__ int   g_off[MAXM + 1];
__device__ int   g_cursor[MAXM];
__device__ int   g_csr[MAXET];
__device__ float g_xlA[(size_t)MP * D];
__device__ float g_xrA[(size_t)MP * D];
__device__ float g_xlC[(size_t)MP * D];
__device__ float g_xrC[(size_t)MP * D];
__device__ float g_hA [(size_t)MP * D];
__device__ float g_hC [(size_t)MP * D];
__device__ float g_lg[64 * CH];

// ---------------- CSR build --------------------------------------------------
__global__ void k_hist(const int* __restrict__ tgt, int E, int M) {
    int stride = gridDim.x * blockDim.x;
    int ET = E + M;
    for (int i = blockIdx.x * blockDim.x + threadIdx.x; i < ET; i += stride) {
        int t = (i < E) ? tgt[i] : (i - E);
        atomicAdd(&g_count[t], 1);
    }
}

__global__ void k_scan(int M) {  // single block, 1024 threads
    __shared__ int sh[1024];
    int tid = threadIdx.x;
    int chunk = (M + 1023) >> 10;
    int beg = tid * chunk;
    int end = min(beg + chunk, M);
    int s = 0;
    for (int i = beg; i < end; i++) s += g_count[i];
    sh[tid] = s;
    __syncthreads();
    for (int o = 1; o < 1024; o <<= 1) {
        int v = (tid >= o) ? sh[tid - o] : 0;
        __syncthreads();
        sh[tid] += v;
        __syncthreads();
    }
    int run = sh[tid] - s;
    for (int i = beg; i < end; i++) {
        g_off[i] = run;
        g_cursor[i] = run;
        run += g_count[i];
    }
    if (tid == 1023) g_off[M] = sh[1023];
}

__global__ void k_scatter(const int* __restrict__ src, const int* __restrict__ tgt,
                          int E, int M) {
    int stride = gridDim.x * blockDim.x;
    int ET = E + M;
    for (int i = blockIdx.x * blockDim.x + threadIdx.x; i < ET; i += stride) {
        int t, s;
        if (i < E) { t = tgt[i]; s = src[i]; }
        else       { t = i - E;  s = i - E; }
        int pos = atomicAdd(&g_cursor[t], 1);
        g_csr[pos] = s;
    }
}

// warp-per-node segment sort: bitonic shfl network for deg<=32 (covers
// essentially all nodes at Poisson(17)); lane-0 insertion fallback above.
// Deterministic CSR order -> bitwise-stable downstream accumulation.
__global__ void k_sortwarp(int M) {
    int w = (blockIdx.x * blockDim.x + threadIdx.x) >> 5;
    if (w >= M) return;
    int lane = threadIdx.x & 31;
    int beg = g_off[w], end = g_off[w + 1];
    int deg = end - beg;
    if (deg <= 1) return;
    if (deg <= 32) {
        int v = (lane < deg) ? g_csr[beg + lane] : 0x7fffffff;
        #pragma unroll
        for (int k = 2; k <= 32; k <<= 1) {
            #pragma unroll
            for (int j = k >> 1; j > 0; j >>= 1) {
                int partner = __shfl_xor_sync(0xffffffffu, v, j);
                bool dir   = ((lane & k) == 0);
                bool lower = ((lane & j) == 0);
                v = (lower == dir) ? min(v, partner) : max(v, partner);
            }
        }
        if (lane < deg) g_csr[beg + lane] = v;
    } else if (lane == 0) {
        for (int i = beg + 1; i < end; i++) {
            int v = g_csr[i]; int j = i - 1;
            while (j >= beg && g_csr[j] > v) { g_csr[j + 1] = g_csr[j]; j--; }
            g_csr[j + 1] = v;
        }
    }
}

// ---------------- bf16x3 tensor-core multi-GEMM ------------------------------
#define LDB 136
#define LDC 132

__device__ __forceinline__ void split_store4(float4 v, __nv_bfloat16* hi,
                                             __nv_bfloat16* lo, int idx) {
    __nv_bfloat16 h0 = __float2bfloat16(v.x), h1 = __float2bfloat16(v.y),
                  h2 = __float2bfloat16(v.z), h3 = __float2bfloat16(v.w);
    float l0 = v.x - __bfloat162float(h0), l1 = v.y - __bfloat162float(h1),
          l2 = v.z - __bfloat162float(h2), l3 = v.w - __bfloat162float(h3);
    __nv_bfloat162 hp0 = __halves2bfloat162(h0, h1), hp1 = __halves2bfloat162(h2, h3);
    uint2 hv; hv.x = *(unsigned*)&hp0; hv.y = *(unsigned*)&hp1;
    *(uint2*)&hi[idx] = hv;
    __nv_bfloat162 lp0 = __floats2bfloat162_rn(l0, l1), lp1 = __floats2bfloat162_rn(l2, l3);
    uint2 lv; lv.x = *(unsigned*)&lp0; lv.y = *(unsigned*)&lp1;
    *(uint2*)&lo[idx] = lv;
}

__global__ void k_gemmN(const float* __restrict__ A,
                        const float* __restrict__ W0, const float* __restrict__ b0,
                        float* __restrict__ C0,
                        const float* __restrict__ W1, const float* __restrict__ b1,
                        float* __restrict__ C1,
                        const float* __restrict__ W2, const float* __restrict__ b2,
                        float* __restrict__ C2,
                        const float* __restrict__ W3, const float* __restrict__ b3,
                        float* __restrict__ C3,
                        int M, int npass) {
    extern __shared__ char smraw[];
    __nv_bfloat16* Ahi = (__nv_bfloat16*)smraw;
    __nv_bfloat16* Alo = Ahi + 128 * LDB;
    __nv_bfloat16* Whi = Alo + 128 * LDB;
    __nv_bfloat16* Wlo = Whi + 128 * LDB;
    float* Cs = (float*)Whi;  // overlay: 128*132*4 = 67584 <= 69632
    __shared__ float bsm[4][128];

    int tid = threadIdx.x;       // 256
    int row0 = blockIdx.x * 128;
    int r = tid >> 1, half = tid & 1;
    int cbase = half * 64;

    const float* Wt[4] = {W0, W1, W2, W3};
    const float* bt[4] = {b0, b1, b2, b3};
    float*       Ct[4] = {C0, C1, C2, C3};
    if (tid < 128)
        for (int p = 0; p < npass; p++) bsm[p][tid] = bt[p][tid];

    // ---- fill A hi/lo (once) ----
    {
        int row = row0 + r;
        const float* ap = A + (size_t)row * D + cbase;
        #pragma unroll
        for (int q = 0; q < 16; q++) {
            float4 v = (row < M) ? *(const float4*)(ap + q * 4)
                                 : make_float4(0.f, 0.f, 0.f, 0.f);
            split_store4(v, Ahi, Alo, r * LDB + cbase + q * 4);
        }
    }

    int w  = tid >> 5;
    int wr = w >> 2, wc = w & 3;   // warp tile: 64 rows x 32 cols

    for (int pass = 0; pass < npass; pass++) {
        const float* W = Wt[pass];
        float* C       = Ct[pass];

        if (pass > 0) __syncthreads();
        {
            const float* wp = W + r * D + cbase;
            #pragma unroll
            for (int q = 0; q < 16; q++)
                split_store4(*(const float4*)(wp + q * 4), Whi, Wlo,
                             r * LDB + cbase + q * 4);
        }
        __syncthreads();

        wmma::fragment<wmma::accumulator, 16, 16, 16, float> acc[4][2];
        #pragma unroll
        for (int m = 0; m < 4; m++)
            #pragma unroll
            for (int n = 0; n < 2; n++) wmma::fill_fragment(acc[m][n], 0.f);

        wmma::fragment<wmma::matrix_a, 16, 16, 16, __nv_bfloat16, wmma::row_major> ah[4], al[4];
        wmma::fragment<wmma::matrix_b, 16, 16, 16, __nv_bfloat16, wmma::row_major> bh[2], bl[2];

        #pragma unroll
        for (int kk = 0; kk < 8; kk++) {
            int k0 = kk * 16;
            #pragma unroll
            for (int n = 0; n < 2; n++) {
                wmma::load_matrix_sync(bh[n], &Whi[k0 * LDB + wc * 32 + n * 16], LDB);
                wmma::load_matrix_sync(bl[n], &Wlo[k0 * LDB + wc * 32 + n * 16], LDB);
            }
            #pragma unroll
            for (int m = 0; m < 4; m++) {
                wmma::load_matrix_sync(ah[m], &Ahi[(wr * 64 + m * 16) * LDB + k0], LDB);
                wmma::load_matrix_sync(al[m], &Alo[(wr * 64 + m * 16) * LDB + k0], LDB);
            }
            #pragma unroll
            for (int m = 0; m < 4; m++)
                #pragma unroll
                for (int n = 0; n < 2; n++) {
                    wmma::mma_sync(acc[m][n], ah[m], bl[n], acc[m][n]);
                    wmma::mma_sync(acc[m][n], al[m], bh[n], acc[m][n]);
                    wmma::mma_sync(acc[m][n], ah[m], bh[n], acc[m][n]);
                }
        }
        __syncthreads();

        #pragma unroll
        for (int m = 0; m < 4; m++)
            #pragma unroll
            for (int n = 0; n < 2; n++)
                wmma::store_matrix_sync(&Cs[(wr * 64 + m * 16) * LDC + wc * 32 + n * 16],
                                        acc[m][n], LDC, wmma::mem_row_major);
        __syncthreads();

        {
            int row = row0 + r;
            if (row < M) {
                #pragma unroll
                for (int q = 0; q < 16; q++) {
                    int c = cbase + q * 4;
                    float4 v = *(float4*)&Cs[r * LDC + c];
                    v.x += bsm[pass][c]; v.y += bsm[pass][c + 1];
                    v.z += bsm[pass][c + 2]; v.w += bsm[pass][c + 3];
                    *(float4*)&C[(size_t)row * D + c] = v;
                }
            }
        }
    }
}

// ---------------- GATv2 aggregate, Dout=128 (prefetch-pipelined) -------------
// one warp per target node, lane = 4 channels, warp-uniform online softmax.
// next edge's row is loaded before the current edge's softmax chain.
__global__ void k_gat128d(
    const float* __restrict__ xlA, const float* __restrict__ xrA,
    const float* __restrict__ attA, const float* __restrict__ biasA,
    float* __restrict__ outA,
    const float* __restrict__ xlC, const float* __restrict__ xrC,
    const float* __restrict__ attC, const float* __restrict__ biasC,
    float* __restrict__ outC,
    int M, float slope) {
    int w = (blockIdx.x * blockDim.x + threadIdx.x) >> 5;
    if (w >= M) return;
    const float *xl, *xr, *att, *bias; float* out;
    if (blockIdx.y == 0) { xl = xlA; xr = xrA; att = attA; bias = biasA; out = outA; }
    else                 { xl = xlC; xr = xrC; att = attC; bias = biasC; out = outC; }
    int lane = threadIdx.x & 31;

    float4 xr4 = *(const float4*)(xr + (size_t)w * D + lane * 4);
    float4 at4 = *(const float4*)(att + lane * 4);
    int beg = g_off[w], end = g_off[w + 1];   // deg >= 1 (self loop)

    float m = -INFINITY, d = 0.f;
    float4 acc = make_float4(0.f, 0.f, 0.f, 0.f);

    float4 aCur = *(const float4*)(xl + (size_t)g_csr[beg] * D + lane * 4);
    int sNext = (beg + 1 < end) ? g_csr[beg + 1] : 0;

    for (int e = beg; e < end; e++) {
        float4 a = aCur;
        if (e + 1 < end) {
            aCur = *(const float4*)(xl + (size_t)sNext * D + lane * 4);
            if (e + 2 < end) sNext = g_csr[e + 2];
        }
        float t0 = a.x + xr4.x; t0 = (t0 > 0.f) ? t0 : 0.2f * t0;
        float t1 = a.y + xr4.y; t1 = (t1 > 0.f) ? t1 : 0.2f * t1;
        float t2 = a.z + xr4.z; t2 = (t2 > 0.f) ? t2 : 0.2f * t2;
        float t3 = a.w + xr4.w; t3 = (t3 > 0.f) ? t3 : 0.2f * t3;
        float p = t0 * at4.x + t1 * at4.y + t2 * at4.z + t3 * at4.w;
        #pragma unroll
        for (int o = 16; o; o >>= 1) p += __shfl_xor_sync(0xffffffffu, p, o);

        if (p <= m) {
            float wgt = __expf(p - m);
            d += wgt;
            acc.x += wgt * a.x; acc.y += wgt * a.y;
            acc.z += wgt * a.z; acc.w += wgt * a.w;
        } else {
            float c1 = __expf(m - p);
            d = d * c1 + 1.f;
            acc.x = acc.x * c1 + a.x; acc.y = acc.y * c1 + a.y;
            acc.z = acc.z * c1 + a.z; acc.w = acc.w * c1 + a.w;
            m = p;
        }
    }

    float inv = 1.f / (d + 1e-16f);
    float4 b4 = *(const float4*)(bias + lane * 4);
    float o0 = acc.x * inv + b4.x;
    float o1 = acc.y * inv + b4.y;
    float o2 = acc.z * inv + b4.z;
    float o3 = acc.w * inv + b4.w;
    o0 = (o0 > 0.f) ? o0 : slope * o0;
    o1 = (o1 > 0.f) ? o1 : slope * o1;
    o2 = (o2 > 0.f) ? o2 : slope * o2;
    o3 = (o3 > 0.f) ? o3 : slope * o3;
    *(float4*)(out + (size_t)w * D + lane * 4) = make_float4(o0, o1, o2, o3);
}

// ---------------- c2 GATv2 + fused value head (prefetch-pipelined) -----------
__global__ void k_gatV(
    const float* __restrict__ xl, const float* __restrict__ xr,
    const float* __restrict__ att, const float* __restrict__ bias,
    const float* __restrict__ fcW, const float* __restrict__ fcb,
    float* __restrict__ value, int M) {
    int w = (blockIdx.x * blockDim.x + threadIdx.x) >> 5;
    if (w >= M) return;
    int lane = threadIdx.x & 31;

    float4 xr4 = *(const float4*)(xr + (size_t)w * D + lane * 4);
    float4 at4 = *(const float4*)(att + lane * 4);
    int beg = g_off[w], end = g_off[w + 1];

    float m = -INFINITY, d = 0.f;
    float4 acc = make_float4(0.f, 0.f, 0.f, 0.f);

    float4 aCur = *(const float4*)(xl + (size_t)g_csr[beg] * D + lane * 4);
    int sNext = (beg + 1 < end) ? g_csr[beg + 1] : 0;

    for (int e = beg; e < end; e++) {
        float4 a = aCur;
        if (e + 1 < end) {
            aCur = *(const float4*)(xl + (size_t)sNext * D + lane * 4);
            if (e + 2 < end) sNext = g_csr[e + 2];
        }
        float t0 = a.x + xr4.x; t0 = (t0 > 0.f) ? t0 : 0.2f * t0;
        float t1 = a.y + xr4.y; t1 = (t1 > 0.f) ? t1 : 0.2f * t1;
        float t2 = a.z + xr4.z; t2 = (t2 > 0.f) ? t2 : 0.2f * t2;
        float t3 = a.w + xr4.w; t3 = (t3 > 0.f) ? t3 : 0.2f * t3;
        float p = t0 * at4.x + t1 * at4.y + t2 * at4.z + t3 * at4.w;
        #pragma unroll
        for (int o = 16; o; o >>= 1) p += __shfl_xor_sync(0xffffffffu, p, o);

        if (p <= m) {
            float wgt = __expf(p - m);
            d += wgt;
            acc.x += wgt * a.x; acc.y += wgt * a.y;
            acc.z += wgt * a.z; acc.w += wgt * a.w;
        } else {
            float c1 = __expf(m - p);
            d = d * c1 + 1.f;
            acc.x = acc.x * c1 + a.x; acc.y = acc.y * c1 + a.y;
            acc.z = acc.z * c1 + a.z; acc.w = acc.w * c1 + a.w;
            m = p;
        }
    }

    float inv = 1.f / (d + 1e-16f);
    float4 b4 = *(const float4*)(bias + lane * 4);
    float4 fw = *(const float4*)(fcW + lane * 4);
    float v = (acc.x * inv + b4.x) * fw.x
            + (acc.y * inv + b4.y) * fw.y
            + (acc.z * inv + b4.z) * fw.z
            + (acc.w * inv + b4.w) * fw.w;
    #pragma unroll
    for (int o = 16; o; o >>= 1) v += __shfl_xor_sync(0xffffffffu, v, o);
    if (lane == 0) value[w] = v + fcb[0];
}

// ---------------- fused actor head: a2 projections + gat7 on 32 targets ------
// Only the 32 sampled rows' logits are ever used; compute s1[src]/s2[tgt]
// on the fly for their ~550 incident edges instead of all 40k rows.
// One block (1 warp) per target.
__global__ void k_actorhead(const float* __restrict__ h,
                            const float* __restrict__ W1, const float* __restrict__ b1,
                            const float* __restrict__ W2, const float* __restrict__ b2,
                            const float* __restrict__ att, const float* __restrict__ bias,
                            float* __restrict__ lg, int B, int N) {
    __shared__ float W1s[D * CH], W2s[D * CH];
    int t = blockIdx.x;          // 0..B*NC-1
    int lane = threadIdx.x;      // 32 threads
    for (int i = lane; i < D * CH; i += 32) { W1s[i] = W1[i]; W2s[i] = W2[i]; }
    __syncwarp();

    int row = (t >> 3) * N + (t & 7);
    int k0 = lane * 4;

    // s2 = h[row] @ W2 + b2  (broadcast to all lanes via butterfly)
    float4 hr = *(const float4*)(h + (size_t)row * D + k0);
    float s2v[CH], attv[CH], b1v[CH];
    #pragma unroll
    for (int c = 0; c < CH; c++) {
        float p = hr.x * W2s[(k0 + 0) * CH + c] + hr.y * W2s[(k0 + 1) * CH + c]
                + hr.z * W2s[(k0 + 2) * CH + c] + hr.w * W2s[(k0 + 3) * CH + c];
        #pragma unroll
        for (int o = 16; o; o >>= 1) p += __shfl_xor_sync(0xffffffffu, p, o);
        s2v[c] = p + b2[c];
        attv[c] = att[c];
        b1v[c] = b1[c];
    }

    int beg = g_off[row], end = g_off[row + 1];
    float m = -INFINITY, d = 0.f;
    float acc[CH];
    #pragma unroll
    for (int c = 0; c < CH; c++) acc[c] = 0.f;

    for (int e = beg; e < end; e++) {
        int s = g_csr[e];
        float4 hs = *(const float4*)(h + (size_t)s * D + k0);
        float s1v[CH];
        #pragma unroll
        for (int c = 0; c < CH; c++) {
            float p = hs.x * W1s[(k0 + 0) * CH + c] + hs.y * W1s[(k0 + 1) * CH + c]
                    + hs.z * W1s[(k0 + 2) * CH + c] + hs.w * W1s[(k0 + 3) * CH + c];
            #pragma unroll
            for (int o = 16; o; o >>= 1) p += __shfl_xor_sync(0xffffffffu, p, o);
            s1v[c] = p + b1v[c];
        }
        float sc = 0.f;
        #pragma unroll
        for (int c = 0; c < CH; c++) {
            float tt = s1v[c] + s2v[c];
            tt = (tt > 0.f) ? tt : 0.2f * tt;
            sc = fmaf(tt, attv[c], sc);
        }
        if (sc <= m) {
            float wgt = __expf(sc - m);
            d += wgt;
            #pragma unroll
            for (int c = 0; c < CH; c++) acc[c] = fmaf(wgt, s1v[c], acc[c]);
        } else {
            float c1 = __expf(m - sc);
            d = d * c1 + 1.f;
            #pragma unroll
            for (int c = 0; c < CH; c++) acc[c] = acc[c] * c1 + s1v[c];
            m = sc;
        }
    }
    if (lane == 0) {
        float inv = 1.f / (d + 1e-16f);
        for (int c = 0; c < CH; c++)
            lg[t * CH + c] = acc[c] * inv + bias[c];
    }
}

// ---------------- actor head: softmax + gumbel + top-4 + sel -----------------
__global__ void k_actor(const float* __restrict__ logits, const float* __restrict__ gu,
                        float* __restrict__ out, int B, int N) {
    __shared__ float shp[4][NC][CH];
    int tid = threadIdx.x;            // 32 threads
    int b = tid >> 3, i = tid & 7;
    bool active = tid < B * NC;
    if (active) {
        float l[CH], mx = -INFINITY;
        for (int c = 0; c < CH; c++) { l[c] = logits[tid * CH + c]; mx = fmaxf(mx, l[c]); }
        float s = 0.f;
        for (int c = 0; c < CH; c++) { l[c] = expf(l[c] - mx); s += l[c]; }
        for (int c = 0; c < CH; c++) shp[b][i][c] = l[c] / s;
    }
    __syncthreads();
    if (active) {
        float sc[CH];
        for (int c = 0; c < CH; c++) {
            float u = gu[(b * NC + i) * CH + c];
            float g = -logf(-logf(u));
            sc[c] = logf(shp[b][i][c]) + g;
        }
        int base = (b * NC + i) * NS;
        int seloff = B * NC * NS;
        for (int j = 0; j < NS; j++) {
            int best = 0; float bv = -INFINITY;
            for (int c = 0; c < CH; c++)
                if (sc[c] > bv) { bv = sc[c]; best = c; }
            out[base + j] = (float)best;
            out[seloff + base + j] = shp[b][best][j];
            sc[best] = -INFINITY;
        }
    }
}

// ---------------- launch -----------------------------------------------------
extern "C" void kernel_launch(void* const* d_in, const int* in_sizes, int n_in,
                              void* d_out, int out_size) {
    const float* x  = (const float*)d_in[0];
    const int*   ei = (const int*)d_in[1];
    const float* gu = (const float*)d_in[2];
    const float* Wp[4][6];
    for (int l = 0; l < 4; l++)
        for (int j = 0; j < 6; j++)
            Wp[l][j] = (const float*)d_in[3 + l * 6 + j];
    const float* fcW = (const float*)d_in[27];
    const float* fcb = (const float*)d_in[28];

    int M = in_sizes[0] / D;
    int E = in_sizes[1] / 2;
    int B = in_sizes[2] / (NC * CH);
    int N = M / B;
    int ET = E + M;
    float* out = (float*)d_out;

    void *pc, *pxlA, *pxrA, *pxlC, *pxrC, *phA, *phC, *plg;
    cudaGetSymbolAddress(&pc,   g_count);
    cudaGetSymbolAddress(&pxlA, g_xlA);
    cudaGetSymbolAddress(&pxrA, g_xrA);
    cudaGetSymbolAddress(&pxlC, g_xlC);
    cudaGetSymbolAddress(&pxrC, g_xrC);
    cudaGetSymbolAddress(&phA,  g_hA);
    cudaGetSymbolAddress(&phC,  g_hC);
    cudaGetSymbolAddress(&plg,  g_lg);
    float* xlA = (float*)pxlA; float* xrA = (float*)pxrA;
    float* xlC = (float*)pxlC; float* xrC = (float*)pxrC;
    float* hA  = (float*)phA;  float* hC  = (float*)phC;
    float* lg  = (float*)plg;

    const int tb = 256;
    // ---- CSR build (shared by all GAT layers) ----
    cudaMemsetAsync(pc, 0, (size_t)(M + 1) * sizeof(int));
    int gE = (ET + tb - 1) / tb; if (gE > 4096) gE = 4096;
    k_hist<<<gE, tb>>>(ei + E, E, M);
    k_scan<<<1, 1024>>>(M);
    k_scatter<<<gE, tb>>>(ei, ei + E, E, M);
    int gws = (M * 32 + tb - 1) / tb;
    k_sortwarp<<<gws, tb>>>(M);

    // ---- GEMM config ----
    size_t smemN = (size_t)4 * 128 * LDB * sizeof(__nv_bfloat16);  // 139264
    cudaFuncSetAttribute(k_gemmN, cudaFuncAttributeMaxDynamicSharedMemorySize, (int)smemN);
    int gg  = (M + 127) / 128;
    int gwB = (M * 32 + tb - 1) / tb;

    // ---- layer 1 (actor a1 + critic c1): 4 projections, A split once ----
    k_gemmN<<<gg, tb, smemN>>>(x,
                               Wp[0][0], Wp[0][1], xlA,
                               Wp[0][2], Wp[0][3], xrA,
                               Wp[2][0], Wp[2][1], xlC,
                               Wp[2][2], Wp[2][3], xrC, M, 4);
    k_gat128d<<<dim3(gwB, 2), tb>>>(xlA, xrA, Wp[0][4], Wp[0][5], hA,
                                    xlC, xrC, Wp[2][4], Wp[2][5], hC,
                                    M, 0.01f);

    // ---- actor head: fused a2 projections + gat7 on 32 targets ----
    k_actorhead<<<B * NC, 32>>>(hA, Wp[1][0], Wp[1][1], Wp[1][2], Wp[1][3],
                                Wp[1][4], Wp[1][5], lg, B, N);
    k_actor<<<1, 32>>>(lg, gu, out, B, N);

    // ---- critic layer 2 + value (fused) ----
    k_gemmN<<<gg, tb, smemN>>>(hC,
                               Wp[3][0], Wp[3][1], xlA,
                               Wp[3][2], Wp[3][3], xrA,
                               Wp[3][0], Wp[3][1], xlA,
                               Wp[3][2], Wp[3][3], xrA, M, 2);
    k_gatV<<<gwB, tb>>>(xlA, xrA, Wp[3][4], Wp[3][5],
                        fcW, fcb, out + 2 * B * NC * NS, M);
}

// round 10
// speedup vs baseline: 1.5094x; 1.1603x over previous
#include <cuda_runtime.h>
#include <cuda_bf16.h>
#include <math.h>
#include <mma.h>

using namespace nvcuda;

#define D   128
#define CH  7
#define NC  8
#define NS  4
#define MAXM  40000
#define MP    (MAXM + 128)
#define MAXET 680000

// ---------------- scratch (static device globals; no allocation) -------------
__device__ int   g_count[MAXM + 1];
__device__ int   g_off[MAXM + 1];
__device__ int   g_cursor[MAXM];
__device__ int   g_csr[MAXET];
__device__ float g_xlA[(size_t)MP * D];
__device__ float g_xrA[(size_t)MP * D];
__device__ float g_xlC[(size_t)MP * D];
__device__ float g_xrC[(size_t)MP * D];
__device__ float g_hA [(size_t)MP * D];
__device__ float g_hC [(size_t)MP * D];
__device__ float g_lg[64 * CH];

// ---------------- CSR build --------------------------------------------------
__global__ void k_hist(const int* __restrict__ tgt, int E, int M) {
    int stride = gridDim.x * blockDim.x;
    int ET = E + M;
    for (int i = blockIdx.x * blockDim.x + threadIdx.x; i < ET; i += stride) {
        int t = (i < E) ? tgt[i] : (i - E);
        atomicAdd(&g_count[t], 1);
    }
}

__global__ void k_scan(int M) {  // single block, 1024 threads
    __shared__ int sh[1024];
    int tid = threadIdx.x;
    int chunk = (M + 1023) >> 10;
    int beg = tid * chunk;
    int end = min(beg + chunk, M);
    int s = 0;
    for (int i = beg; i < end; i++) s += g_count[i];
    sh[tid] = s;
    __syncthreads();
    for (int o = 1; o < 1024; o <<= 1) {
        int v = (tid >= o) ? sh[tid - o] : 0;
        __syncthreads();
        sh[tid] += v;
        __syncthreads();
    }
    int run = sh[tid] - s;
    for (int i = beg; i < end; i++) {
        g_off[i] = run;
        g_cursor[i] = run;
        run += g_count[i];
    }
    if (tid == 1023) g_off[M] = sh[1023];
}

__global__ void k_scatter(const int* __restrict__ src, const int* __restrict__ tgt,
                          int E, int M) {
    int stride = gridDim.x * blockDim.x;
    int ET = E + M;
    for (int i = blockIdx.x * blockDim.x + threadIdx.x; i < ET; i += stride) {
        int t, s;
        if (i < E) { t = tgt[i]; s = src[i]; }
        else       { t = i - E;  s = i - E; }
        int pos = atomicAdd(&g_cursor[t], 1);
        g_csr[pos] = s;
    }
}

// warp-per-node segment sort (bitonic shfl for deg<=32; insertion fallback).
// Deterministic CSR order -> bitwise-stable downstream accumulation.
__global__ void k_sortwarp(int M) {
    int w = (blockIdx.x * blockDim.x + threadIdx.x) >> 5;
    if (w >= M) return;
    int lane = threadIdx.x & 31;
    int beg = g_off[w], end = g_off[w + 1];
    int deg = end - beg;
    if (deg <= 1) return;
    if (deg <= 32) {
        int v = (lane < deg) ? g_csr[beg + lane] : 0x7fffffff;
        #pragma unroll
        for (int k = 2; k <= 32; k <<= 1) {
            #pragma unroll
            for (int j = k >> 1; j > 0; j >>= 1) {
                int partner = __shfl_xor_sync(0xffffffffu, v, j);
                bool dir   = ((lane & k) == 0);
                bool lower = ((lane & j) == 0);
                v = (lower == dir) ? min(v, partner) : max(v, partner);
            }
        }
        if (lane < deg) g_csr[beg + lane] = v;
    } else if (lane == 0) {
        for (int i = beg + 1; i < end; i++) {
            int v = g_csr[i]; int j = i - 1;
            while (j >= beg && g_csr[j] > v) { g_csr[j + 1] = g_csr[j]; j--; }
            g_csr[j + 1] = v;
        }
    }
}

// ---------------- bf16x3 tensor-core multi-GEMM (no bias, direct store) ------
#define LDB 136

__device__ __forceinline__ void split_store4(float4 v, __nv_bfloat16* hi,
                                             __nv_bfloat16* lo, int idx) {
    __nv_bfloat16 h0 = __float2bfloat16(v.x), h1 = __float2bfloat16(v.y),
                  h2 = __float2bfloat16(v.z), h3 = __float2bfloat16(v.w);
    float l0 = v.x - __bfloat162float(h0), l1 = v.y - __bfloat162float(h1),
          l2 = v.z - __bfloat162float(h2), l3 = v.w - __bfloat162float(h3);
    __nv_bfloat162 hp0 = __halves2bfloat162(h0, h1), hp1 = __halves2bfloat162(h2, h3);
    uint2 hv; hv.x = *(unsigned*)&hp0; hv.y = *(unsigned*)&hp1;
    *(uint2*)&hi[idx] = hv;
    __nv_bfloat162 lp0 = __floats2bfloat162_rn(l0, l1), lp1 = __floats2bfloat162_rn(l2, l3);
    uint2 lv; lv.x = *(unsigned*)&lp0; lv.y = *(unsigned*)&lp1;
    *(uint2*)&lo[idx] = lv;
}

__global__ void k_gemmN(const float* __restrict__ A,
                        const float* __restrict__ W0, float* __restrict__ C0,
                        const float* __restrict__ W1, float* __restrict__ C1,
                        const float* __restrict__ W2, float* __restrict__ C2,
                        const float* __restrict__ W3, float* __restrict__ C3,
                        int M, int npass) {
    extern __shared__ char smraw[];
    __nv_bfloat16* Ahi = (__nv_bfloat16*)smraw;
    __nv_bfloat16* Alo = Ahi + 128 * LDB;
    __nv_bfloat16* Whi = Alo + 128 * LDB;
    __nv_bfloat16* Wlo = Whi + 128 * LDB;

    int tid = threadIdx.x;       // 256
    int row0 = blockIdx.x * 128;
    int r = tid >> 1, half = tid & 1;
    int cbase = half * 64;

    const float* Wt[4] = {W0, W1, W2, W3};
    float*       Ct[4] = {C0, C1, C2, C3};

    // ---- fill A hi/lo (once) ----
    {
        int row = row0 + r;
        const float* ap = A + (size_t)row * D + cbase;
        #pragma unroll
        for (int q = 0; q < 16; q++) {
            float4 v = (row < M) ? *(const float4*)(ap + q * 4)
                                 : make_float4(0.f, 0.f, 0.f, 0.f);
            split_store4(v, Ahi, Alo, r * LDB + cbase + q * 4);
        }
    }

    int w  = tid >> 5;
    int wr = w >> 2, wc = w & 3;   // warp tile: 64 rows x 32 cols

    for (int pass = 0; pass < npass; pass++) {
        const float* W = Wt[pass];
        float* C       = Ct[pass];

        if (pass > 0) __syncthreads();   // all warps done reading prior W
        {
            const float* wp = W + r * D + cbase;
            #pragma unroll
            for (int q = 0; q < 16; q++)
                split_store4(*(const float4*)(wp + q * 4), Whi, Wlo,
                             r * LDB + cbase + q * 4);
        }
        __syncthreads();

        wmma::fragment<wmma::accumulator, 16, 16, 16, float> acc[4][2];
        #pragma unroll
        for (int m = 0; m < 4; m++)
            #pragma unroll
            for (int n = 0; n < 2; n++) wmma::fill_fragment(acc[m][n], 0.f);

        wmma::fragment<wmma::matrix_a, 16, 16, 16, __nv_bfloat16, wmma::row_major> ah[4], al[4];
        wmma::fragment<wmma::matrix_b, 16, 16, 16, __nv_bfloat16, wmma::row_major> bh[2], bl[2];

        #pragma unroll
        for (int kk = 0; kk < 8; kk++) {
            int k0 = kk * 16;
            #pragma unroll
            for (int n = 0; n < 2; n++) {
                wmma::load_matrix_sync(bh[n], &Whi[k0 * LDB + wc * 32 + n * 16], LDB);
                wmma::load_matrix_sync(bl[n], &Wlo[k0 * LDB + wc * 32 + n * 16], LDB);
            }
            #pragma unroll
            for (int m = 0; m < 4; m++) {
                wmma::load_matrix_sync(ah[m], &Ahi[(wr * 64 + m * 16) * LDB + k0], LDB);
                wmma::load_matrix_sync(al[m], &Alo[(wr * 64 + m * 16) * LDB + k0], LDB);
            }
            #pragma unroll
            for (int m = 0; m < 4; m++)
                #pragma unroll
                for (int n = 0; n < 2; n++) {
                    wmma::mma_sync(acc[m][n], ah[m], bl[n], acc[m][n]);
                    wmma::mma_sync(acc[m][n], al[m], bh[n], acc[m][n]);
                    wmma::mma_sync(acc[m][n], ah[m], bh[n], acc[m][n]);
                }
        }

        // direct store to row-padded global (MP rows; full tiles always fit)
        #pragma unroll
        for (int m = 0; m < 4; m++)
            #pragma unroll
            for (int n = 0; n < 2; n++)
                wmma::store_matrix_sync(
                    C + (size_t)(row0 + wr * 64 + m * 16) * D + wc * 32 + n * 16,
                    acc[m][n], D, wmma::mem_row_major);
    }
}

// ---------------- GATv2 aggregate, Dout=128 (bias-folded, prefetch) ----------
// ul/ur are UNBIASED projections; score adds (bl+br) to ur[tgt]; output adds
// (bl + layer_b).  blockIdx.y selects actor/critic set.
__global__ void k_gat128d(
    const float* __restrict__ ulA, const float* __restrict__ urA,
    const float* __restrict__ attA, const float* __restrict__ blA,
    const float* __restrict__ brA, const float* __restrict__ boA,
    float* __restrict__ outA,
    const float* __restrict__ ulC, const float* __restrict__ urC,
    const float* __restrict__ attC, const float* __restrict__ blC,
    const float* __restrict__ brC, const float* __restrict__ boC,
    float* __restrict__ outC,
    int M, float slope) {
    int w = (blockIdx.x * blockDim.x + threadIdx.x) >> 5;
    if (w >= M) return;
    const float *ul, *ur, *att, *bl, *br, *bo; float* out;
    if (blockIdx.y == 0) { ul = ulA; ur = urA; att = attA; bl = blA; br = brA; bo = boA; out = outA; }
    else                 { ul = ulC; ur = urC; att = attC; bl = blC; br = brC; bo = boC; out = outC; }
    int lane = threadIdx.x & 31;

    float4 bl4 = *(const float4*)(bl + lane * 4);
    float4 xr4 = *(const float4*)(ur + (size_t)w * D + lane * 4);
    {
        float4 br4 = *(const float4*)(br + lane * 4);
        xr4.x += bl4.x + br4.x; xr4.y += bl4.y + br4.y;
        xr4.z += bl4.z + br4.z; xr4.w += bl4.w + br4.w;
    }
    float4 at4 = *(const float4*)(att + lane * 4);
    int beg = g_off[w], end = g_off[w + 1];   // deg >= 1 (self loop)

    float m = -INFINITY, d = 0.f;
    float4 acc = make_float4(0.f, 0.f, 0.f, 0.f);

    float4 aCur = *(const float4*)(ul + (size_t)g_csr[beg] * D + lane * 4);
    int sNext = (beg + 1 < end) ? g_csr[beg + 1] : 0;

    for (int e = beg; e < end; e++) {
        float4 a = aCur;
        if (e + 1 < end) {
            aCur = *(const float4*)(ul + (size_t)sNext * D + lane * 4);
            if (e + 2 < end) sNext = g_csr[e + 2];
        }
        float t0 = a.x + xr4.x; t0 = (t0 > 0.f) ? t0 : 0.2f * t0;
        float t1 = a.y + xr4.y; t1 = (t1 > 0.f) ? t1 : 0.2f * t1;
        float t2 = a.z + xr4.z; t2 = (t2 > 0.f) ? t2 : 0.2f * t2;
        float t3 = a.w + xr4.w; t3 = (t3 > 0.f) ? t3 : 0.2f * t3;
        float p = t0 * at4.x + t1 * at4.y + t2 * at4.z + t3 * at4.w;
        #pragma unroll
        for (int o = 16; o; o >>= 1) p += __shfl_xor_sync(0xffffffffu, p, o);

        if (p <= m) {
            float wgt = __expf(p - m);
            d += wgt;
            acc.x += wgt * a.x; acc.y += wgt * a.y;
            acc.z += wgt * a.z; acc.w += wgt * a.w;
        } else {
            float c1 = __expf(m - p);
            d = d * c1 + 1.f;
            acc.x = acc.x * c1 + a.x; acc.y = acc.y * c1 + a.y;
            acc.z = acc.z * c1 + a.z; acc.w = acc.w * c1 + a.w;
            m = p;
        }
    }

    float inv = 1.f / (d + 1e-16f);
    float4 bo4 = *(const float4*)(bo + lane * 4);
    float o0 = acc.x * inv + bl4.x + bo4.x;
    float o1 = acc.y * inv + bl4.y + bo4.y;
    float o2 = acc.z * inv + bl4.z + bo4.z;
    float o3 = acc.w * inv + bl4.w + bo4.w;
    o0 = (o0 > 0.f) ? o0 : slope * o0;
    o1 = (o1 > 0.f) ? o1 : slope * o1;
    o2 = (o2 > 0.f) ? o2 : slope * o2;
    o3 = (o3 > 0.f) ? o3 : slope * o3;
    *(float4*)(out + (size_t)w * D + lane * 4) = make_float4(o0, o1, o2, o3);
}

// ---------------- c2 GATv2 + fused value head (bias-folded, prefetch) --------
__global__ void k_gatV(
    const float* __restrict__ ul, const float* __restrict__ ur,
    const float* __restrict__ att, const float* __restrict__ bl,
    const float* __restrict__ br, const float* __restrict__ bo,
    const float* __restrict__ fcW, const float* __restrict__ fcb,
    float* __restrict__ value, int M) {
    int w = (blockIdx.x * blockDim.x + threadIdx.x) >> 5;
    if (w >= M) return;
    int lane = threadIdx.x & 31;

    float4 bl4 = *(const float4*)(bl + lane * 4);
    float4 xr4 = *(const float4*)(ur + (size_t)w * D + lane * 4);
    {
        float4 br4 = *(const float4*)(br + lane * 4);
        xr4.x += bl4.x + br4.x; xr4.y += bl4.y + br4.y;
        xr4.z += bl4.z + br4.z; xr4.w += bl4.w + br4.w;
    }
    float4 at4 = *(const float4*)(att + lane * 4);
    int beg = g_off[w], end = g_off[w + 1];

    float m = -INFINITY, d = 0.f;
    float4 acc = make_float4(0.f, 0.f, 0.f, 0.f);

    float4 aCur = *(const float4*)(ul + (size_t)g_csr[beg] * D + lane * 4);
    int sNext = (beg + 1 < end) ? g_csr[beg + 1] : 0;

    for (int e = beg; e < end; e++) {
        float4 a = aCur;
        if (e + 1 < end) {
            aCur = *(const float4*)(ul + (size_t)sNext * D + lane * 4);
            if (e + 2 < end) sNext = g_csr[e + 2];
        }
        float t0 = a.x + xr4.x; t0 = (t0 > 0.f) ? t0 : 0.2f * t0;
        float t1 = a.y + xr4.y; t1 = (t1 > 0.f) ? t1 : 0.2f * t1;
        float t2 = a.z + xr4.z; t2 = (t2 > 0.f) ? t2 : 0.2f * t2;
        float t3 = a.w + xr4.w; t3 = (t3 > 0.f) ? t3 : 0.2f * t3;
        float p = t0 * at4.x + t1 * at4.y + t2 * at4.z + t3 * at4.w;
        #pragma unroll
        for (int o = 16; o; o >>= 1) p += __shfl_xor_sync(0xffffffffu, p, o);

        if (p <= m) {
            float wgt = __expf(p - m);
            d += wgt;
            acc.x += wgt * a.x; acc.y += wgt * a.y;
            acc.z += wgt * a.z; acc.w += wgt * a.w;
        } else {
            float c1 = __expf(m - p);
            d = d * c1 + 1.f;
            acc.x = acc.x * c1 + a.x; acc.y = acc.y * c1 + a.y;
            acc.z = acc.z * c1 + a.z; acc.w = acc.w * c1 + a.w;
            m = p;
        }
    }

    float inv = 1.f / (d + 1e-16f);
    float4 bo4 = *(const float4*)(bo + lane * 4);
    float4 fw = *(const float4*)(fcW + lane * 4);
    float v = (acc.x * inv + bl4.x + bo4.x) * fw.x
            + (acc.y * inv + bl4.y + bo4.y) * fw.y
            + (acc.z * inv + bl4.z + bo4.z) * fw.z
            + (acc.w * inv + bl4.w + bo4.w) * fw.w;
    #pragma unroll
    for (int o = 16; o; o >>= 1) v += __shfl_xor_sync(0xffffffffu, v, o);
    if (lane == 0) value[w] = v + fcb[0];
}

// ---------------- fused actor head: a2 projections + gat7 on 32 targets ------
__global__ void k_actorhead(const float* __restrict__ h,
                            const float* __restrict__ W1, const float* __restrict__ b1,
                            const float* __restrict__ W2, const float* __restrict__ b2,
                            const float* __restrict__ att, const float* __restrict__ bias,
                            float* __restrict__ lg, int B, int N) {
    __shared__ float W1s[D * CH], W2s[D * CH];
    int t = blockIdx.x;          // 0..B*NC-1
    int lane = threadIdx.x;      // 32 threads
    for (int i = lane; i < D * CH; i += 32) { W1s[i] = W1[i]; W2s[i] = W2[i]; }
    __syncwarp();

    int row = (t >> 3) * N + (t & 7);
    int k0 = lane * 4;

    float4 hr = *(const float4*)(h + (size_t)row * D + k0);
    float s2v[CH], attv[CH], b1v[CH];
    #pragma unroll
    for (int c = 0; c < CH; c++) {
        float p = hr.x * W2s[(k0 + 0) * CH + c] + hr.y * W2s[(k0 + 1) * CH + c]
                + hr.z * W2s[(k0 + 2) * CH + c] + hr.w * W2s[(k0 + 3) * CH + c];
        #pragma unroll
        for (int o = 16; o; o >>= 1) p += __shfl_xor_sync(0xffffffffu, p, o);
        s2v[c] = p + b2[c];
        attv[c] = att[c];
        b1v[c] = b1[c];
    }

    int beg = g_off[row], end = g_off[row + 1];
    float m = -INFINITY, d = 0.f;
    float acc[CH];
    #pragma unroll
    for (int c = 0; c < CH; c++) acc[c] = 0.f;

    for (int e = beg; e < end; e++) {
        int s = g_csr[e];
        float4 hs = *(const float4*)(h + (size_t)s * D + k0);
        float s1v[CH];
        #pragma unroll
        for (int c = 0; c < CH; c++) {
            float p = hs.x * W1s[(k0 + 0) * CH + c] + hs.y * W1s[(k0 + 1) * CH + c]
                    + hs.z * W1s[(k0 + 2) * CH + c] + hs.w * W1s[(k0 + 3) * CH + c];
            #pragma unroll
            for (int o = 16; o; o >>= 1) p += __shfl_xor_sync(0xffffffffu, p, o);
            s1v[c] = p + b1v[c];
        }
        float sc = 0.f;
        #pragma unroll
        for (int c = 0; c < CH; c++) {
            float tt = s1v[c] + s2v[c];
            tt = (tt > 0.f) ? tt : 0.2f * tt;
            sc = fmaf(tt, attv[c], sc);
        }
        if (sc <= m) {
            float wgt = __expf(sc - m);
            d += wgt;
            #pragma unroll
            for (int c = 0; c < CH; c++) acc[c] = fmaf(wgt, s1v[c], acc[c]);
        } else {
            float c1 = __expf(m - sc);
            d = d * c1 + 1.f;
            #pragma unroll
            for (int c = 0; c < CH; c++) acc[c] = acc[c] * c1 + s1v[c];
            m = sc;
        }
    }
    if (lane == 0) {
        float inv = 1.f / (d + 1e-16f);
        for (int c = 0; c < CH; c++)
            lg[t * CH + c] = acc[c] * inv + bias[c];
    }
}

// ---------------- actor head: softmax + gumbel + top-4 + sel -----------------
__global__ void k_actor(const float* __restrict__ logits, const float* __restrict__ gu,
                        float* __restrict__ out, int B, int N) {
    __shared__ float shp[4][NC][CH];
    int tid = threadIdx.x;            // 32 threads
    int b = tid >> 3, i = tid & 7;
    bool active = tid < B * NC;
    if (active) {
        float l[CH], mx = -INFINITY;
        for (int c = 0; c < CH; c++) { l[c] = logits[tid * CH + c]; mx = fmaxf(mx, l[c]); }
        float s = 0.f;
        for (int c = 0; c < CH; c++) { l[c] = expf(l[c] - mx); s += l[c]; }
        for (int c = 0; c < CH; c++) shp[b][i][c] = l[c] / s;
    }
    __syncthreads();
    if (active) {
        float sc[CH];
        for (int c = 0; c < CH; c++) {
            float u = gu[(b * NC + i) * CH + c];
            float g = -logf(-logf(u));
            sc[c] = logf(shp[b][i][c]) + g;
        }
        int base = (b * NC + i) * NS;
        int seloff = B * NC * NS;
        for (int j = 0; j < NS; j++) {
            int best = 0; float bv = -INFINITY;
            for (int c = 0; c < CH; c++)
                if (sc[c] > bv) { bv = sc[c]; best = c; }
            out[base + j] = (float)best;
            out[seloff + base + j] = shp[b][best][j];
            sc[best] = -INFINITY;
        }
    }
}

// ---------------- launch -----------------------------------------------------
extern "C" void kernel_launch(void* const* d_in, const int* in_sizes, int n_in,
                              void* d_out, int out_size) {
    const float* x  = (const float*)d_in[0];
    const int*   ei = (const int*)d_in[1];
    const float* gu = (const float*)d_in[2];
    const float* Wp[4][6];
    for (int l = 0; l < 4; l++)
        for (int j = 0; j < 6; j++)
            Wp[l][j] = (const float*)d_in[3 + l * 6 + j];
    const float* fcW = (const float*)d_in[27];
    const float* fcb = (const float*)d_in[28];

    int M = in_sizes[0] / D;
    int E = in_sizes[1] / 2;
    int B = in_sizes[2] / (NC * CH);
    int N = M / B;
    int ET = E + M;
    float* out = (float*)d_out;

    // one-time (first/correctness call, before graph capture) stream+event setup
    static cudaStream_t s1 = nullptr, s2 = nullptr;
    static cudaEvent_t evA = nullptr, evB = nullptr, evC = nullptr, evD = nullptr;
    if (!s1) {
        cudaStreamCreateWithFlags(&s1, cudaStreamNonBlocking);
        cudaStreamCreateWithFlags(&s2, cudaStreamNonBlocking);
        cudaEventCreateWithFlags(&evA, cudaEventDisableTiming);
        cudaEventCreateWithFlags(&evB, cudaEventDisableTiming);
        cudaEventCreateWithFlags(&evC, cudaEventDisableTiming);
        cudaEventCreateWithFlags(&evD, cudaEventDisableTiming);
    }

    void *pc, *pxlA, *pxrA, *pxlC, *pxrC, *phA, *phC, *plg;
    cudaGetSymbolAddress(&pc,   g_count);
    cudaGetSymbolAddress(&pxlA, g_xlA);
    cudaGetSymbolAddress(&pxrA, g_xrA);
    cudaGetSymbolAddress(&pxlC, g_xlC);
    cudaGetSymbolAddress(&pxrC, g_xrC);
    cudaGetSymbolAddress(&phA,  g_hA);
    cudaGetSymbolAddress(&phC,  g_hC);
    cudaGetSymbolAddress(&plg,  g_lg);
    float* xlA = (float*)pxlA; float* xrA = (float*)pxrA;
    float* xlC = (float*)pxlC; float* xrC = (float*)pxrC;
    float* hA  = (float*)phA;  float* hC  = (float*)phC;
    float* lg  = (float*)plg;

    const int tb = 256;
    size_t smemN = (size_t)4 * 128 * LDB * sizeof(__nv_bfloat16);  // 139264
    cudaFuncSetAttribute(k_gemmN, cudaFuncAttributeMaxDynamicSharedMemorySize, (int)smemN);
    int gg  = (M + 127) / 128;
    int gwB = (M * 32 + tb - 1) / tb;
    int gE  = (ET + tb - 1) / tb; if (gE > 4096) gE = 4096;
    int gws = (M * 32 + tb - 1) / tb;

    // ---- fork: CSR build (s1) || layer-1 GEMM (main) ----
    cudaEventRecord(evA, 0);
    cudaStreamWaitEvent(s1, evA, 0);

    cudaMemsetAsync(pc, 0, (size_t)(M + 1) * sizeof(int), s1);
    k_hist<<<gE, tb, 0, s1>>>(ei + E, E, M);
    k_scan<<<1, 1024, 0, s1>>>(M);
    k_scatter<<<gE, tb, 0, s1>>>(ei, ei + E, E, M);
    k_sortwarp<<<gws, tb, 0, s1>>>(M);
    cudaEventRecord(evB, s1);

    k_gemmN<<<gg, tb, smemN>>>(x, Wp[0][0], xlA, Wp[0][2], xrA,
                                  Wp[2][0], xlC, Wp[2][2], xrC, M, 4);

    // ---- join, then layer-1 GAT (both paths) ----
    cudaStreamWaitEvent(0, evB, 0);
    k_gat128d<<<dim3(gwB, 2), tb>>>(
        xlA, xrA, Wp[0][4], Wp[0][1], Wp[0][3], Wp[0][5], hA,
        xlC, xrC, Wp[2][4], Wp[2][1], Wp[2][3], Wp[2][5], hC,
        M, 0.01f);

    // ---- fork: actor head (s2) || critic layer-2 (main) ----
    cudaEventRecord(evC, 0);
    cudaStreamWaitEvent(s2, evC, 0);
    k_actorhead<<<B * NC, 32, 0, s2>>>(hA, Wp[1][0], Wp[1][1], Wp[1][2], Wp[1][3],
                                       Wp[1][4], Wp[1][5], lg, B, N);
    k_actor<<<1, 32, 0, s2>>>(lg, gu, out, B, N);
    cudaEventRecord(evD, s2);

    k_gemmN<<<gg, tb, smemN>>>(hC, Wp[3][0], xlA, Wp[3][2], xrA,
                                   Wp[3][0], xlA, Wp[3][2], xrA, M, 2);
    k_gatV<<<gwB, tb>>>(xlA, xrA, Wp[3][4], Wp[3][1], Wp[3][3], Wp[3][5],
                        fcW, fcb, out + 2 * B * NC * NS, M);

    // ---- final join ----
    cudaStreamWaitEvent(0, evD, 0);
}

// round 11
// speedup vs baseline: 1.5285x; 1.0127x over previous
#include <cuda_runtime.h>
#include <cuda_bf16.h>
#include <math.h>
#include <mma.h>

using namespace nvcuda;

#define D   128
#define CH  7
#define NC  8
#define NS  4
#define MAXM  40000
#define MP    (MAXM + 128)
#define MAXET 680000

// ---------------- scratch (static device globals; no allocation) -------------
__device__ int   g_count[MAXM + 1];
__device__ int   g_off[MAXM + 1];
__device__ int   g_cursor[MAXM];
__device__ int   g_csr[MAXET];
__device__ float g_xlA[(size_t)MP * D];
__device__ float g_xrA[(size_t)MP * D];
__device__ float g_xlC[(size_t)MP * D];
__device__ float g_xrC[(size_t)MP * D];
__device__ float g_hA [(size_t)MP * D];
__device__ float g_hC [(size_t)MP * D];
__device__ float g_lg[64 * CH];

// ---------------- CSR build --------------------------------------------------
__global__ void k_hist(const int* __restrict__ tgt, int E, int M) {
    int stride = gridDim.x * blockDim.x;
    int ET = E + M;
    for (int i = blockIdx.x * blockDim.x + threadIdx.x; i < ET; i += stride) {
        int t = (i < E) ? tgt[i] : (i - E);
        atomicAdd(&g_count[t], 1);
    }
}

__global__ void k_scan(int M) {  // single block, 1024 threads
    __shared__ int sh[1024];
    int tid = threadIdx.x;
    int chunk = (M + 1023) >> 10;
    int beg = tid * chunk;
    int end = min(beg + chunk, M);
    int s = 0;
    for (int i = beg; i < end; i++) s += g_count[i];
    sh[tid] = s;
    __syncthreads();
    for (int o = 1; o < 1024; o <<= 1) {
        int v = (tid >= o) ? sh[tid - o] : 0;
        __syncthreads();
        sh[tid] += v;
        __syncthreads();
    }
    int run = sh[tid] - s;
    for (int i = beg; i < end; i++) {
        g_off[i] = run;
        g_cursor[i] = run;
        run += g_count[i];
    }
    if (tid == 1023) g_off[M] = sh[1023];
}

__global__ void k_scatter(const int* __restrict__ src, const int* __restrict__ tgt,
                          int E, int M) {
    int stride = gridDim.x * blockDim.x;
    int ET = E + M;
    for (int i = blockIdx.x * blockDim.x + threadIdx.x; i < ET; i += stride) {
        int t, s;
        if (i < E) { t = tgt[i]; s = src[i]; }
        else       { t = i - E;  s = i - E; }
        int pos = atomicAdd(&g_cursor[t], 1);
        g_csr[pos] = s;
    }
}

// warp-per-node segment sort (bitonic shfl for deg<=32; insertion fallback).
// Deterministic CSR order -> bitwise-stable downstream accumulation.
__global__ void k_sortwarp(int M) {
    int w = (blockIdx.x * blockDim.x + threadIdx.x) >> 5;
    if (w >= M) return;
    int lane = threadIdx.x & 31;
    int beg = g_off[w], end = g_off[w + 1];
    int deg = end - beg;
    if (deg <= 1) return;
    if (deg <= 32) {
        int v = (lane < deg) ? g_csr[beg + lane] : 0x7fffffff;
        #pragma unroll
        for (int k = 2; k <= 32; k <<= 1) {
            #pragma unroll
            for (int j = k >> 1; j > 0; j >>= 1) {
                int partner = __shfl_xor_sync(0xffffffffu, v, j);
                bool dir   = ((lane & k) == 0);
                bool lower = ((lane & j) == 0);
                v = (lower == dir) ? min(v, partner) : max(v, partner);
            }
        }
        if (lane < deg) g_csr[beg + lane] = v;
    } else if (lane == 0) {
        for (int i = beg + 1; i < end; i++) {
            int v = g_csr[i]; int j = i - 1;
            while (j >= beg && g_csr[j] > v) { g_csr[j + 1] = g_csr[j]; j--; }
            g_csr[j + 1] = v;
        }
    }
}

// ---------------- bf16x3 tensor-core multi-GEMM (no bias, direct store) ------
#define LDB 136

__device__ __forceinline__ void split_store4(float4 v, __nv_bfloat16* hi,
                                             __nv_bfloat16* lo, int idx) {
    __nv_bfloat16 h0 = __float2bfloat16(v.x), h1 = __float2bfloat16(v.y),
                  h2 = __float2bfloat16(v.z), h3 = __float2bfloat16(v.w);
    float l0 = v.x - __bfloat162float(h0), l1 = v.y - __bfloat162float(h1),
          l2 = v.z - __bfloat162float(h2), l3 = v.w - __bfloat162float(h3);
    __nv_bfloat162 hp0 = __halves2bfloat162(h0, h1), hp1 = __halves2bfloat162(h2, h3);
    uint2 hv; hv.x = *(unsigned*)&hp0; hv.y = *(unsigned*)&hp1;
    *(uint2*)&hi[idx] = hv;
    __nv_bfloat162 lp0 = __floats2bfloat162_rn(l0, l1), lp1 = __floats2bfloat162_rn(l2, l3);
    uint2 lv; lv.x = *(unsigned*)&lp0; lv.y = *(unsigned*)&lp1;
    *(uint2*)&lo[idx] = lv;
}

__global__ void k_gemmN(const float* __restrict__ A,
                        const float* __restrict__ W0, float* __restrict__ C0,
                        const float* __restrict__ W1, float* __restrict__ C1,
                        const float* __restrict__ W2, float* __restrict__ C2,
                        const float* __restrict__ W3, float* __restrict__ C3,
                        int M, int npass) {
    extern __shared__ char smraw[];
    __nv_bfloat16* Ahi = (__nv_bfloat16*)smraw;
    __nv_bfloat16* Alo = Ahi + 128 * LDB;
    __nv_bfloat16* Whi = Alo + 128 * LDB;
    __nv_bfloat16* Wlo = Whi + 128 * LDB;

    int tid = threadIdx.x;       // 256
    int row0 = blockIdx.x * 128;
    int r = tid >> 1, half = tid & 1;
    int cbase = half * 64;

    const float* Wt[4] = {W0, W1, W2, W3};
    float*       Ct[4] = {C0, C1, C2, C3};

    // ---- fill A hi/lo (once) ----
    {
        int row = row0 + r;
        const float* ap = A + (size_t)row * D + cbase;
        #pragma unroll
        for (int q = 0; q < 16; q++) {
            float4 v = (row < M) ? *(const float4*)(ap + q * 4)
                                 : make_float4(0.f, 0.f, 0.f, 0.f);
            split_store4(v, Ahi, Alo, r * LDB + cbase + q * 4);
        }
    }

    int w  = tid >> 5;
    int wr = w >> 2, wc = w & 3;   // warp tile: 64 rows x 32 cols

    for (int pass = 0; pass < npass; pass++) {
        const float* W = Wt[pass];
        float* C       = Ct[pass];

        if (pass > 0) __syncthreads();
        {
            const float* wp = W + r * D + cbase;
            #pragma unroll
            for (int q = 0; q < 16; q++)
                split_store4(*(const float4*)(wp + q * 4), Whi, Wlo,
                             r * LDB + cbase + q * 4);
        }
        __syncthreads();

        wmma::fragment<wmma::accumulator, 16, 16, 16, float> acc[4][2];
        #pragma unroll
        for (int m = 0; m < 4; m++)
            #pragma unroll
            for (int n = 0; n < 2; n++) wmma::fill_fragment(acc[m][n], 0.f);

        wmma::fragment<wmma::matrix_a, 16, 16, 16, __nv_bfloat16, wmma::row_major> ah[4], al[4];
        wmma::fragment<wmma::matrix_b, 16, 16, 16, __nv_bfloat16, wmma::row_major> bh[2], bl[2];

        #pragma unroll
        for (int kk = 0; kk < 8; kk++) {
            int k0 = kk * 16;
            #pragma unroll
            for (int n = 0; n < 2; n++) {
                wmma::load_matrix_sync(bh[n], &Whi[k0 * LDB + wc * 32 + n * 16], LDB);
                wmma::load_matrix_sync(bl[n], &Wlo[k0 * LDB + wc * 32 + n * 16], LDB);
            }
            #pragma unroll
            for (int m = 0; m < 4; m++) {
                wmma::load_matrix_sync(ah[m], &Ahi[(wr * 64 + m * 16) * LDB + k0], LDB);
                wmma::load_matrix_sync(al[m], &Alo[(wr * 64 + m * 16) * LDB + k0], LDB);
            }
            #pragma unroll
            for (int m = 0; m < 4; m++)
                #pragma unroll
                for (int n = 0; n < 2; n++) {
                    wmma::mma_sync(acc[m][n], ah[m], bl[n], acc[m][n]);
                    wmma::mma_sync(acc[m][n], al[m], bh[n], acc[m][n]);
                    wmma::mma_sync(acc[m][n], ah[m], bh[n], acc[m][n]);
                }
        }

        // direct store to row-padded global (MP rows; full tiles always fit)
        #pragma unroll
        for (int m = 0; m < 4; m++)
            #pragma unroll
            for (int n = 0; n < 2; n++)
                wmma::store_matrix_sync(
                    C + (size_t)(row0 + wr * 64 + m * 16) * D + wc * 32 + n * 16,
                    acc[m][n], D, wmma::mem_row_major);
    }
}

// ---------------- GATv2 aggregate, Dout=128 (bias-folded, prefetch) ----------
// ul/ur are UNBIASED projections; score adds (bl+br) to ur[tgt]; output adds
// (bl + layer_b), then leaky-relu(slope).
__global__ void k_gat1(
    const float* __restrict__ ul, const float* __restrict__ ur,
    const float* __restrict__ att, const float* __restrict__ bl,
    const float* __restrict__ br, const float* __restrict__ bo,
    float* __restrict__ out, int M, float slope) {
    int w = (blockIdx.x * blockDim.x + threadIdx.x) >> 5;
    if (w >= M) return;
    int lane = threadIdx.x & 31;

    float4 bl4 = *(const float4*)(bl + lane * 4);
    float4 xr4 = *(const float4*)(ur + (size_t)w * D + lane * 4);
    {
        float4 br4 = *(const float4*)(br + lane * 4);
        xr4.x += bl4.x + br4.x; xr4.y += bl4.y + br4.y;
        xr4.z += bl4.z + br4.z; xr4.w += bl4.w + br4.w;
    }
    float4 at4 = *(const float4*)(att + lane * 4);
    int beg = g_off[w], end = g_off[w + 1];   // deg >= 1 (self loop)

    float m = -INFINITY, d = 0.f;
    float4 acc = make_float4(0.f, 0.f, 0.f, 0.f);

    float4 aCur = *(const float4*)(ul + (size_t)g_csr[beg] * D + lane * 4);
    int sNext = (beg + 1 < end) ? g_csr[beg + 1] : 0;

    for (int e = beg; e < end; e++) {
        float4 a = aCur;
        if (e + 1 < end) {
            aCur = *(const float4*)(ul + (size_t)sNext * D + lane * 4);
            if (e + 2 < end) sNext = g_csr[e + 2];
        }
        float t0 = a.x + xr4.x; t0 = (t0 > 0.f) ? t0 : 0.2f * t0;
        float t1 = a.y + xr4.y; t1 = (t1 > 0.f) ? t1 : 0.2f * t1;
        float t2 = a.z + xr4.z; t2 = (t2 > 0.f) ? t2 : 0.2f * t2;
        float t3 = a.w + xr4.w; t3 = (t3 > 0.f) ? t3 : 0.2f * t3;
        float p = t0 * at4.x + t1 * at4.y + t2 * at4.z + t3 * at4.w;
        #pragma unroll
        for (int o = 16; o; o >>= 1) p += __shfl_xor_sync(0xffffffffu, p, o);

        if (p <= m) {
            float wgt = __expf(p - m);
            d += wgt;
            acc.x += wgt * a.x; acc.y += wgt * a.y;
            acc.z += wgt * a.z; acc.w += wgt * a.w;
        } else {
            float c1 = __expf(m - p);
            d = d * c1 + 1.f;
            acc.x = acc.x * c1 + a.x; acc.y = acc.y * c1 + a.y;
            acc.z = acc.z * c1 + a.z; acc.w = acc.w * c1 + a.w;
            m = p;
        }
    }

    float inv = 1.f / (d + 1e-16f);
    float4 bo4 = *(const float4*)(bo + lane * 4);
    float o0 = acc.x * inv + bl4.x + bo4.x;
    float o1 = acc.y * inv + bl4.y + bo4.y;
    float o2 = acc.z * inv + bl4.z + bo4.z;
    float o3 = acc.w * inv + bl4.w + bo4.w;
    o0 = (o0 > 0.f) ? o0 : slope * o0;
    o1 = (o1 > 0.f) ? o1 : slope * o1;
    o2 = (o2 > 0.f) ? o2 : slope * o2;
    o3 = (o3 > 0.f) ? o3 : slope * o3;
    *(float4*)(out + (size_t)w * D + lane * 4) = make_float4(o0, o1, o2, o3);
}

// ---------------- c2 GATv2 + fused value head (bias-folded, prefetch) --------
__global__ void k_gatV(
    const float* __restrict__ ul, const float* __restrict__ ur,
    const float* __restrict__ att, const float* __restrict__ bl,
    const float* __restrict__ br, const float* __restrict__ bo,
    const float* __restrict__ fcW, const float* __restrict__ fcb,
    float* __restrict__ value, int M) {
    int w = (blockIdx.x * blockDim.x + threadIdx.x) >> 5;
    if (w >= M) return;
    int lane = threadIdx.x & 31;

    float4 bl4 = *(const float4*)(bl + lane * 4);
    float4 xr4 = *(const float4*)(ur + (size_t)w * D + lane * 4);
    {
        float4 br4 = *(const float4*)(br + lane * 4);
        xr4.x += bl4.x + br4.x; xr4.y += bl4.y + br4.y;
        xr4.z += bl4.z + br4.z; xr4.w += bl4.w + br4.w;
    }
    float4 at4 = *(const float4*)(att + lane * 4);
    int beg = g_off[w], end = g_off[w + 1];

    float m = -INFINITY, d = 0.f;
    float4 acc = make_float4(0.f, 0.f, 0.f, 0.f);

    float4 aCur = *(const float4*)(ul + (size_t)g_csr[beg] * D + lane * 4);
    int sNext = (beg + 1 < end) ? g_csr[beg + 1] : 0;

    for (int e = beg; e < end; e++) {
        float4 a = aCur;
        if (e + 1 < end) {
            aCur = *(const float4*)(ul + (size_t)sNext * D + lane * 4);
            if (e + 2 < end) sNext = g_csr[e + 2];
        }
        float t0 = a.x + xr4.x; t0 = (t0 > 0.f) ? t0 : 0.2f * t0;
        float t1 = a.y + xr4.y; t1 = (t1 > 0.f) ? t1 : 0.2f * t1;
        float t2 = a.z + xr4.z; t2 = (t2 > 0.f) ? t2 : 0.2f * t2;
        float t3 = a.w + xr4.w; t3 = (t3 > 0.f) ? t3 : 0.2f * t3;
        float p = t0 * at4.x + t1 * at4.y + t2 * at4.z + t3 * at4.w;
        #pragma unroll
        for (int o = 16; o; o >>= 1) p += __shfl_xor_sync(0xffffffffu, p, o);

        if (p <= m) {
            float wgt = __expf(p - m);
            d += wgt;
            acc.x += wgt * a.x; acc.y += wgt * a.y;
            acc.z += wgt * a.z; acc.w += wgt * a.w;
        } else {
            float c1 = __expf(m - p);
            d = d * c1 + 1.f;
            acc.x = acc.x * c1 + a.x; acc.y = acc.y * c1 + a.y;
            acc.z = acc.z * c1 + a.z; acc.w = acc.w * c1 + a.w;
            m = p;
        }
    }

    float inv = 1.f / (d + 1e-16f);
    float4 bo4 = *(const float4*)(bo + lane * 4);
    float4 fw = *(const float4*)(fcW + lane * 4);
    float v = (acc.x * inv + bl4.x + bo4.x) * fw.x
            + (acc.y * inv + bl4.y + bo4.y) * fw.y
            + (acc.z * inv + bl4.z + bo4.z) * fw.z
            + (acc.w * inv + bl4.w + bo4.w) * fw.w;
    #pragma unroll
    for (int o = 16; o; o >>= 1) v += __shfl_xor_sync(0xffffffffu, v, o);
    if (lane == 0) value[w] = v + fcb[0];
}

// ---------------- fused actor head: a2 projections + gat7 on 32 targets ------
__global__ void k_actorhead(const float* __restrict__ h,
                            const float* __restrict__ W1, const float* __restrict__ b1,
                            const float* __restrict__ W2, const float* __restrict__ b2,
                            const float* __restrict__ att, const float* __restrict__ bias,
                            float* __restrict__ lg, int B, int N) {
    __shared__ float W1s[D * CH], W2s[D * CH];
    int t = blockIdx.x;          // 0..B*NC-1
    int lane = threadIdx.x;      // 32 threads
    for (int i = lane; i < D * CH; i += 32) { W1s[i] = W1[i]; W2s[i] = W2[i]; }
    __syncwarp();

    int row = (t >> 3) * N + (t & 7);
    int k0 = lane * 4;

    float4 hr = *(const float4*)(h + (size_t)row * D + k0);
    float s2v[CH], attv[CH], b1v[CH];
    #pragma unroll
    for (int c = 0; c < CH; c++) {
        float p = hr.x * W2s[(k0 + 0) * CH + c] + hr.y * W2s[(k0 + 1) * CH + c]
                + hr.z * W2s[(k0 + 2) * CH + c] + hr.w * W2s[(k0 + 3) * CH + c];
        #pragma unroll
        for (int o = 16; o; o >>= 1) p += __shfl_xor_sync(0xffffffffu, p, o);
        s2v[c] = p + b2[c];
        attv[c] = att[c];
        b1v[c] = b1[c];
    }

    int beg = g_off[row], end = g_off[row + 1];
    float m = -INFINITY, d = 0.f;
    float acc[CH];
    #pragma unroll
    for (int c = 0; c < CH; c++) acc[c] = 0.f;

    for (int e = beg; e < end; e++) {
        int s = g_csr[e];
        float4 hs = *(const float4*)(h + (size_t)s * D + k0);
        float s1v[CH];
        #pragma unroll
        for (int c = 0; c < CH; c++) {
            float p = hs.x * W1s[(k0 + 0) * CH + c] + hs.y * W1s[(k0 + 1) * CH + c]
                    + hs.z * W1s[(k0 + 2) * CH + c] + hs.w * W1s[(k0 + 3) * CH + c];
            #pragma unroll
            for (int o = 16; o; o >>= 1) p += __shfl_xor_sync(0xffffffffu, p, o);
            s1v[c] = p + b1v[c];
        }
        float sc = 0.f;
        #pragma unroll
        for (int c = 0; c < CH; c++) {
            float tt = s1v[c] + s2v[c];
            tt = (tt > 0.f) ? tt : 0.2f * tt;
            sc = fmaf(tt, attv[c], sc);
        }
        if (sc <= m) {
            float wgt = __expf(sc - m);
            d += wgt;
            #pragma unroll
            for (int c = 0; c < CH; c++) acc[c] = fmaf(wgt, s1v[c], acc[c]);
        } else {
            float c1 = __expf(m - sc);
            d = d * c1 + 1.f;
            #pragma unroll
            for (int c = 0; c < CH; c++) acc[c] = acc[c] * c1 + s1v[c];
            m = sc;
        }
    }
    if (lane == 0) {
        float inv = 1.f / (d + 1e-16f);
        for (int c = 0; c < CH; c++)
            lg[t * CH + c] = acc[c] * inv + bias[c];
    }
}

// ---------------- actor head: softmax + gumbel + top-4 + sel -----------------
__global__ void k_actor(const float* __restrict__ logits, const float* __restrict__ gu,
                        float* __restrict__ out, int B, int N) {
    __shared__ float shp[4][NC][CH];
    int tid = threadIdx.x;            // 32 threads
    int b = tid >> 3, i = tid & 7;
    bool active = tid < B * NC;
    if (active) {
        float l[CH], mx = -INFINITY;
        for (int c = 0; c < CH; c++) { l[c] = logits[tid * CH + c]; mx = fmaxf(mx, l[c]); }
        float s = 0.f;
        for (int c = 0; c < CH; c++) { l[c] = expf(l[c] - mx); s += l[c]; }
        for (int c = 0; c < CH; c++) shp[b][i][c] = l[c] / s;
    }
    __syncthreads();
    if (active) {
        float sc[CH];
        for (int c = 0; c < CH; c++) {
            float u = gu[(b * NC + i) * CH + c];
            float g = -logf(-logf(u));
            sc[c] = logf(shp[b][i][c]) + g;
        }
        int base = (b * NC + i) * NS;
        int seloff = B * NC * NS;
        for (int j = 0; j < NS; j++) {
            int best = 0; float bv = -INFINITY;
            for (int c = 0; c < CH; c++)
                if (sc[c] > bv) { bv = sc[c]; best = c; }
            out[base + j] = (float)best;
            out[seloff + base + j] = shp[b][best][j];
            sc[best] = -INFINITY;
        }
    }
}

// ---------------- launch -----------------------------------------------------
extern "C" void kernel_launch(void* const* d_in, const int* in_sizes, int n_in,
                              void* d_out, int out_size) {
    const float* x  = (const float*)d_in[0];
    const int*   ei = (const int*)d_in[1];
    const float* gu = (const float*)d_in[2];
    const float* Wp[4][6];
    for (int l = 0; l < 4; l++)
        for (int j = 0; j < 6; j++)
            Wp[l][j] = (const float*)d_in[3 + l * 6 + j];
    const float* fcW = (const float*)d_in[27];
    const float* fcb = (const float*)d_in[28];

    int M = in_sizes[0] / D;
    int E = in_sizes[1] / 2;
    int B = in_sizes[2] / (NC * CH);
    int N = M / B;
    int ET = E + M;
    float* out = (float*)d_out;

    // one-time (first/correctness call, before graph capture) stream+event setup
    static cudaStream_t s1 = nullptr, s2 = nullptr;
    static cudaEvent_t evA = nullptr, evB = nullptr, evC = nullptr, evD = nullptr;
    if (!s1) {
        cudaStreamCreateWithFlags(&s1, cudaStreamNonBlocking);
        cudaStreamCreateWithFlags(&s2, cudaStreamNonBlocking);
        cudaEventCreateWithFlags(&evA, cudaEventDisableTiming);
        cudaEventCreateWithFlags(&evB, cudaEventDisableTiming);
        cudaEventCreateWithFlags(&evC, cudaEventDisableTiming);
        cudaEventCreateWithFlags(&evD, cudaEventDisableTiming);
    }

    void *pc, *pxlA, *pxrA, *pxlC, *pxrC, *phA, *phC, *plg;
    cudaGetSymbolAddress(&pc,   g_count);
    cudaGetSymbolAddress(&pxlA, g_xlA);
    cudaGetSymbolAddress(&pxrA, g_xrA);
    cudaGetSymbolAddress(&pxlC, g_xlC);
    cudaGetSymbolAddress(&pxrC, g_xrC);
    cudaGetSymbolAddress(&phA,  g_hA);
    cudaGetSymbolAddress(&phC,  g_hC);
    cudaGetSymbolAddress(&plg,  g_lg);
    float* xlA = (float*)pxlA; float* xrA = (float*)pxrA;
    float* xlC = (float*)pxlC; float* xrC = (float*)pxrC;
    float* hA  = (float*)phA;  float* hC  = (float*)phC;
    float* lg  = (float*)plg;

    const int tb = 256;
    size_t smemN = (size_t)4 * 128 * LDB * sizeof(__nv_bfloat16);  // 139264
    cudaFuncSetAttribute(k_gemmN, cudaFuncAttributeMaxDynamicSharedMemorySize, (int)smemN);
    int gg  = (M + 127) / 128;
    int gwB = (M * 32 + tb - 1) / tb;
    int gE  = (ET + tb - 1) / tb; if (gE > 4096) gE = 4096;
    int gws = (M * 32 + tb - 1) / tb;

    // ---- fork: CSR build (s1) || layer-1 GEMM (main) ----
    cudaEventRecord(evA, 0);
    cudaStreamWaitEvent(s1, evA, 0);

    cudaMemsetAsync(pc, 0, (size_t)(M + 1) * sizeof(int), s1);
    k_hist<<<gE, tb, 0, s1>>>(ei + E, E, M);
    k_scan<<<1, 1024, 0, s1>>>(M);
    k_scatter<<<gE, tb, 0, s1>>>(ei, ei + E, E, M);
    k_sortwarp<<<gws, tb, 0, s1>>>(M);
    cudaEventRecord(evB, s1);

    k_gemmN<<<gg, tb, smemN>>>(x, Wp[0][0], xlA, Wp[0][2], xrA,
                                  Wp[2][0], xlC, Wp[2][2], xrC, M, 4);

    // ---- join CSR, then critic gat ALONE (full L2 bandwidth) ----
    cudaStreamWaitEvent(0, evB, 0);
    k_gat1<<<gwB, tb>>>(xlC, xrC, Wp[2][4], Wp[2][1], Wp[2][3], Wp[2][5],
                        hC, M, 0.01f);
    cudaEventRecord(evC, 0);

    // ---- fork: actor gat + head (s2) || critic layer-2 GEMM + gatV (main) ---
    // gemm2 scratch = xlC/xrC (dead after gatC); actor path reads xlA/xrA -> no race
    cudaStreamWaitEvent(s2, evC, 0);
    k_gat1<<<gwB, tb, 0, s2>>>(xlA, xrA, Wp[0][4], Wp[0][1], Wp[0][3], Wp[0][5],
                               hA, M, 0.01f);
    k_actorhead<<<B * NC, 32, 0, s2>>>(hA, Wp[1][0], Wp[1][1], Wp[1][2], Wp[1][3],
                                       Wp[1][4], Wp[1][5], lg, B, N);
    k_actor<<<1, 32, 0, s2>>>(lg, gu, out, B, N);
    cudaEventRecord(evD, s2);

    k_gemmN<<<gg, tb, smemN>>>(hC, Wp[3][0], xlC, Wp[3][2], xrC,
                                   Wp[3][0], xlC, Wp[3][2], xrC, M, 2);
    k_gatV<<<gwB, tb>>>(xlC, xrC, Wp[3][4], Wp[3][1], Wp[3][3], Wp[3][5],
                        fcW, fcb, out + 2 * B * NC * NS, M);

    // ---- final join ----
    cudaStreamWaitEvent(0, evD, 0);
}

// round 12
// speedup vs baseline: 1.6652x; 1.0895x over previous
#include <cuda_runtime.h>
#include <cuda_bf16.h>
#include <math.h>
#include <mma.h>

using namespace nvcuda;

#define D   128
#define CH  7
#define NC  8
#define NS  4
#define MAXM  40000
#define MP    (MAXM + 128)
#define MAXET 680000
#define WLMAX 8192

// ---------------- scratch (static device globals; no allocation) -------------
__device__ int   g_count[MAXM + 1];
__device__ int   g_off[MAXM + 1];
__device__ int   g_cursor[MAXM];
__device__ int   g_csr[MAXET];
__device__ int   g_wl[WLMAX];
__device__ int   g_wlcount;
__device__ float g_xlA[(size_t)MP * D];
__device__ float g_xrA[(size_t)MP * D];
__device__ float g_xlC[(size_t)MP * D];
__device__ float g_xrC[(size_t)MP * D];
__device__ float g_hA [(size_t)MP * D];
__device__ float g_hC [(size_t)MP * D];
__device__ float g_lg[64 * CH];

// ---------------- CSR build --------------------------------------------------
__global__ void k_hist(const int* __restrict__ tgt, int E, int M) {
    int stride = gridDim.x * blockDim.x;
    int ET = E + M;
    for (int i = blockIdx.x * blockDim.x + threadIdx.x; i < ET; i += stride) {
        int t = (i < E) ? tgt[i] : (i - E);
        atomicAdd(&g_count[t], 1);
    }
}

__global__ void k_scan(int M) {  // single block, 1024 threads
    __shared__ int sh[1024];
    int tid = threadIdx.x;
    int chunk = (M + 1023) >> 10;
    int beg = tid * chunk;
    int end = min(beg + chunk, M);
    int s = 0;
    for (int i = beg; i < end; i++) s += g_count[i];
    sh[tid] = s;
    __syncthreads();
    for (int o = 1; o < 1024; o <<= 1) {
        int v = (tid >= o) ? sh[tid - o] : 0;
        __syncthreads();
        sh[tid] += v;
        __syncthreads();
    }
    int run = sh[tid] - s;
    for (int i = beg; i < end; i++) {
        g_off[i] = run;
        g_cursor[i] = run;
        run += g_count[i];
    }
    if (tid == 1023) g_off[M] = sh[1023];
}

__global__ void k_scatter(const int* __restrict__ src, const int* __restrict__ tgt,
                          int E, int M) {
    int stride = gridDim.x * blockDim.x;
    int ET = E + M;
    for (int i = blockIdx.x * blockDim.x + threadIdx.x; i < ET; i += stride) {
        int t, s;
        if (i < E) { t = tgt[i]; s = src[i]; }
        else       { t = i - E;  s = i - E; }
        int pos = atomicAdd(&g_cursor[t], 1);
        g_csr[pos] = s;
    }
}

// warp-per-node segment sort (bitonic shfl for deg<=32; insertion fallback).
__global__ void k_sortwarp(int M) {
    int w = (blockIdx.x * blockDim.x + threadIdx.x) >> 5;
    if (w >= M) return;
    int lane = threadIdx.x & 31;
    int beg = g_off[w], end = g_off[w + 1];
    int deg = end - beg;
    if (deg <= 1) return;
    if (deg <= 32) {
        int v = (lane < deg) ? g_csr[beg + lane] : 0x7fffffff;
        #pragma unroll
        for (int k = 2; k <= 32; k <<= 1) {
            #pragma unroll
            for (int j = k >> 1; j > 0; j >>= 1) {
                int partner = __shfl_xor_sync(0xffffffffu, v, j);
                bool dir   = ((lane & k) == 0);
                bool lower = ((lane & j) == 0);
                v = (lower == dir) ? min(v, partner) : max(v, partner);
            }
        }
        if (lane < deg) g_csr[beg + lane] = v;
    } else if (lane == 0) {
        for (int i = beg + 1; i < end; i++) {
            int v = g_csr[i]; int j = i - 1;
            while (j >= beg && g_csr[j] > v) { g_csr[j + 1] = g_csr[j]; j--; }
            g_csr[j + 1] = v;
        }
    }
}

// ---------------- actor worklist: 32 targets + their sources -----------------
// one warp per target; order across warps is arbitrary but per-node results
// are independent & deterministic.
__global__ void k_mkwl(int B, int N) {
    int t = threadIdx.x >> 5;     // 0..31 (one block, 1024 threads)
    int lane = threadIdx.x & 31;
    if (t >= B * NC) return;
    int row = (t >> 3) * N + (t & 7);
    int beg = g_off[row], end = g_off[row + 1];
    int deg = end - beg;
    int pos = 0;
    if (lane == 0) pos = atomicAdd(&g_wlcount, deg + 1);
    pos = __shfl_sync(0xffffffffu, pos, 0);
    for (int i = lane; i < deg + 1; i += 32) {
        int idx = pos + i;
        if (idx < WLMAX)
            g_wl[idx] = (i == 0) ? row : g_csr[beg + i - 1];
    }
}

// ---------------- bf16x3 tensor-core multi-GEMM (no bias, direct store) ------
#define LDB 136

__device__ __forceinline__ void split_store4(float4 v, __nv_bfloat16* hi,
                                             __nv_bfloat16* lo, int idx) {
    __nv_bfloat16 h0 = __float2bfloat16(v.x), h1 = __float2bfloat16(v.y),
                  h2 = __float2bfloat16(v.z), h3 = __float2bfloat16(v.w);
    float l0 = v.x - __bfloat162float(h0), l1 = v.y - __bfloat162float(h1),
          l2 = v.z - __bfloat162float(h2), l3 = v.w - __bfloat162float(h3);
    __nv_bfloat162 hp0 = __halves2bfloat162(h0, h1), hp1 = __halves2bfloat162(h2, h3);
    uint2 hv; hv.x = *(unsigned*)&hp0; hv.y = *(unsigned*)&hp1;
    *(uint2*)&hi[idx] = hv;
    __nv_bfloat162 lp0 = __floats2bfloat162_rn(l0, l1), lp1 = __floats2bfloat162_rn(l2, l3);
    uint2 lv; lv.x = *(unsigned*)&lp0; lv.y = *(unsigned*)&lp1;
    *(uint2*)&lo[idx] = lv;
}

__global__ void k_gemmN(const float* __restrict__ A,
                        const float* __restrict__ W0, float* __restrict__ C0,
                        const float* __restrict__ W1, float* __restrict__ C1,
                        const float* __restrict__ W2, float* __restrict__ C2,
                        const float* __restrict__ W3, float* __restrict__ C3,
                        int M, int npass) {
    extern __shared__ char smraw[];
    __nv_bfloat16* Ahi = (__nv_bfloat16*)smraw;
    __nv_bfloat16* Alo = Ahi + 128 * LDB;
    __nv_bfloat16* Whi = Alo + 128 * LDB;
    __nv_bfloat16* Wlo = Whi + 128 * LDB;

    int tid = threadIdx.x;       // 256
    int row0 = blockIdx.x * 128;
    int r = tid >> 1, half = tid & 1;
    int cbase = half * 64;

    const float* Wt[4] = {W0, W1, W2, W3};
    float*       Ct[4] = {C0, C1, C2, C3};

    {
        int row = row0 + r;
        const float* ap = A + (size_t)row * D + cbase;
        #pragma unroll
        for (int q = 0; q < 16; q++) {
            float4 v = (row < M) ? *(const float4*)(ap + q * 4)
                                 : make_float4(0.f, 0.f, 0.f, 0.f);
            split_store4(v, Ahi, Alo, r * LDB + cbase + q * 4);
        }
    }

    int w  = tid >> 5;
    int wr = w >> 2, wc = w & 3;   // warp tile: 64 rows x 32 cols

    for (int pass = 0; pass < npass; pass++) {
        const float* W = Wt[pass];
        float* C       = Ct[pass];

        if (pass > 0) __syncthreads();
        {
            const float* wp = W + r * D + cbase;
            #pragma unroll
            for (int q = 0; q < 16; q++)
                split_store4(*(const float4*)(wp + q * 4), Whi, Wlo,
                             r * LDB + cbase + q * 4);
        }
        __syncthreads();

        wmma::fragment<wmma::accumulator, 16, 16, 16, float> acc[4][2];
        #pragma unroll
        for (int m = 0; m < 4; m++)
            #pragma unroll
            for (int n = 0; n < 2; n++) wmma::fill_fragment(acc[m][n], 0.f);

        wmma::fragment<wmma::matrix_a, 16, 16, 16, __nv_bfloat16, wmma::row_major> ah[4], al[4];
        wmma::fragment<wmma::matrix_b, 16, 16, 16, __nv_bfloat16, wmma::row_major> bh[2], bl[2];

        #pragma unroll
        for (int kk = 0; kk < 8; kk++) {
            int k0 = kk * 16;
            #pragma unroll
            for (int n = 0; n < 2; n++) {
                wmma::load_matrix_sync(bh[n], &Whi[k0 * LDB + wc * 32 + n * 16], LDB);
                wmma::load_matrix_sync(bl[n], &Wlo[k0 * LDB + wc * 32 + n * 16], LDB);
            }
            #pragma unroll
            for (int m = 0; m < 4; m++) {
                wmma::load_matrix_sync(ah[m], &Ahi[(wr * 64 + m * 16) * LDB + k0], LDB);
                wmma::load_matrix_sync(al[m], &Alo[(wr * 64 + m * 16) * LDB + k0], LDB);
            }
            #pragma unroll
            for (int m = 0; m < 4; m++)
                #pragma unroll
                for (int n = 0; n < 2; n++) {
                    wmma::mma_sync(acc[m][n], ah[m], bl[n], acc[m][n]);
                    wmma::mma_sync(acc[m][n], al[m], bh[n], acc[m][n]);
                    wmma::mma_sync(acc[m][n], ah[m], bh[n], acc[m][n]);
                }
        }

        #pragma unroll
        for (int m = 0; m < 4; m++)
            #pragma unroll
            for (int n = 0; n < 2; n++)
                wmma::store_matrix_sync(
                    C + (size_t)(row0 + wr * 64 + m * 16) * D + wc * 32 + n * 16,
                    acc[m][n], D, wmma::mem_row_major);
    }
}

// ---------------- GATv2 node body (bias-folded, prefetch) --------------------
__device__ __forceinline__ void gat_node(
    int w, int lane,
    const float* __restrict__ ul, const float* __restrict__ ur,
    const float* __restrict__ att, const float* __restrict__ bl,
    const float* __restrict__ br, const float* __restrict__ bo,
    float* __restrict__ out, float slope) {
    float4 bl4 = *(const float4*)(bl + lane * 4);
    float4 xr4 = *(const float4*)(ur + (size_t)w * D + lane * 4);
    {
        float4 br4 = *(const float4*)(br + lane * 4);
        xr4.x += bl4.x + br4.x; xr4.y += bl4.y + br4.y;
        xr4.z += bl4.z + br4.z; xr4.w += bl4.w + br4.w;
    }
    float4 at4 = *(const float4*)(att + lane * 4);
    int beg = g_off[w], end = g_off[w + 1];

    float m = -INFINITY, d = 0.f;
    float4 acc = make_float4(0.f, 0.f, 0.f, 0.f);

    float4 aCur = *(const float4*)(ul + (size_t)g_csr[beg] * D + lane * 4);
    int sNext = (beg + 1 < end) ? g_csr[beg + 1] : 0;

    for (int e = beg; e < end; e++) {
        float4 a = aCur;
        if (e + 1 < end) {
            aCur = *(const float4*)(ul + (size_t)sNext * D + lane * 4);
            if (e + 2 < end) sNext = g_csr[e + 2];
        }
        float t0 = a.x + xr4.x; t0 = (t0 > 0.f) ? t0 : 0.2f * t0;
        float t1 = a.y + xr4.y; t1 = (t1 > 0.f) ? t1 : 0.2f * t1;
        float t2 = a.z + xr4.z; t2 = (t2 > 0.f) ? t2 : 0.2f * t2;
        float t3 = a.w + xr4.w; t3 = (t3 > 0.f) ? t3 : 0.2f * t3;
        float p = t0 * at4.x + t1 * at4.y + t2 * at4.z + t3 * at4.w;
        #pragma unroll
        for (int o = 16; o; o >>= 1) p += __shfl_xor_sync(0xffffffffu, p, o);

        if (p <= m) {
            float wgt = __expf(p - m);
            d += wgt;
            acc.x += wgt * a.x; acc.y += wgt * a.y;
            acc.z += wgt * a.z; acc.w += wgt * a.w;
        } else {
            float c1 = __expf(m - p);
            d = d * c1 + 1.f;
            acc.x = acc.x * c1 + a.x; acc.y = acc.y * c1 + a.y;
            acc.z = acc.z * c1 + a.z; acc.w = acc.w * c1 + a.w;
            m = p;
        }
    }

    float inv = 1.f / (d + 1e-16f);
    float4 bo4 = *(const float4*)(bo + lane * 4);
    float o0 = acc.x * inv + bl4.x + bo4.x;
    float o1 = acc.y * inv + bl4.y + bo4.y;
    float o2 = acc.z * inv + bl4.z + bo4.z;
    float o3 = acc.w * inv + bl4.w + bo4.w;
    o0 = (o0 > 0.f) ? o0 : slope * o0;
    o1 = (o1 > 0.f) ? o1 : slope * o1;
    o2 = (o2 > 0.f) ? o2 : slope * o2;
    o3 = (o3 > 0.f) ? o3 : slope * o3;
    *(float4*)(out + (size_t)w * D + lane * 4) = make_float4(o0, o1, o2, o3);
}

// gat over node range [w0, wEnd)
__global__ void k_gat1(
    const float* __restrict__ ul, const float* __restrict__ ur,
    const float* __restrict__ att, const float* __restrict__ bl,
    const float* __restrict__ br, const float* __restrict__ bo,
    float* __restrict__ out, int w0, int wEnd, float slope) {
    int w = w0 + ((blockIdx.x * blockDim.x + threadIdx.x) >> 5);
    if (w >= wEnd) return;
    gat_node(w, threadIdx.x & 31, ul, ur, att, bl, br, bo, out, slope);
}

// gat over the actor worklist (tiny)
__global__ void k_gat1wl(
    const float* __restrict__ ul, const float* __restrict__ ur,
    const float* __restrict__ att, const float* __restrict__ bl,
    const float* __restrict__ br, const float* __restrict__ bo,
    float* __restrict__ out, float slope) {
    int idx = (blockIdx.x * blockDim.x + threadIdx.x) >> 5;
    int n = g_wlcount; if (n > WLMAX) n = WLMAX;
    if (idx >= n) return;
    gat_node(g_wl[idx], threadIdx.x & 31, ul, ur, att, bl, br, bo, out, slope);
}

// ---------------- c2 GATv2 + fused value head --------------------------------
__global__ void k_gatV(
    const float* __restrict__ ul, const float* __restrict__ ur,
    const float* __restrict__ att, const float* __restrict__ bl,
    const float* __restrict__ br, const float* __restrict__ bo,
    const float* __restrict__ fcW, const float* __restrict__ fcb,
    float* __restrict__ value, int M) {
    int w = (blockIdx.x * blockDim.x + threadIdx.x) >> 5;
    if (w >= M) return;
    int lane = threadIdx.x & 31;

    float4 bl4 = *(const float4*)(bl + lane * 4);
    float4 xr4 = *(const float4*)(ur + (size_t)w * D + lane * 4);
    {
        float4 br4 = *(const float4*)(br + lane * 4);
        xr4.x += bl4.x + br4.x; xr4.y += bl4.y + br4.y;
        xr4.z += bl4.z + br4.z; xr4.w += bl4.w + br4.w;
    }
    float4 at4 = *(const float4*)(att + lane * 4);
    int beg = g_off[w], end = g_off[w + 1];

    float m = -INFINITY, d = 0.f;
    float4 acc = make_float4(0.f, 0.f, 0.f, 0.f);

    float4 aCur = *(const float4*)(ul + (size_t)g_csr[beg] * D + lane * 4);
    int sNext = (beg + 1 < end) ? g_csr[beg + 1] : 0;

    for (int e = beg; e < end; e++) {
        float4 a = aCur;
        if (e + 1 < end) {
            aCur = *(const float4*)(ul + (size_t)sNext * D + lane * 4);
            if (e + 2 < end) sNext = g_csr[e + 2];
        }
        float t0 = a.x + xr4.x; t0 = (t0 > 0.f) ? t0 : 0.2f * t0;
        float t1 = a.y + xr4.y; t1 = (t1 > 0.f) ? t1 : 0.2f * t1;
        float t2 = a.z + xr4.z; t2 = (t2 > 0.f) ? t2 : 0.2f * t2;
        float t3 = a.w + xr4.w; t3 = (t3 > 0.f) ? t3 : 0.2f * t3;
        float p = t0 * at4.x + t1 * at4.y + t2 * at4.z + t3 * at4.w;
        #pragma unroll
        for (int o = 16; o; o >>= 1) p += __shfl_xor_sync(0xffffffffu, p, o);

        if (p <= m) {
            float wgt = __expf(p - m);
            d += wgt;
            acc.x += wgt * a.x; acc.y += wgt * a.y;
            acc.z += wgt * a.z; acc.w += wgt * a.w;
        } else {
            float c1 = __expf(m - p);
            d = d * c1 + 1.f;
            acc.x = acc.x * c1 + a.x; acc.y = acc.y * c1 + a.y;
            acc.z = acc.z * c1 + a.z; acc.w = acc.w * c1 + a.w;
            m = p;
        }
    }

    float inv = 1.f / (d + 1e-16f);
    float4 bo4 = *(const float4*)(bo + lane * 4);
    float4 fw = *(const float4*)(fcW + lane * 4);
    float v = (acc.x * inv + bl4.x + bo4.x) * fw.x
            + (acc.y * inv + bl4.y + bo4.y) * fw.y
            + (acc.z * inv + bl4.z + bo4.z) * fw.z
            + (acc.w * inv + bl4.w + bo4.w) * fw.w;
    #pragma unroll
    for (int o = 16; o; o >>= 1) v += __shfl_xor_sync(0xffffffffu, v, o);
    if (lane == 0) value[w] = v + fcb[0];
}

// ---------------- fused actor head: a2 projections + gat7 on 32 targets ------
__global__ void k_actorhead(const float* __restrict__ h,
                            const float* __restrict__ W1, const float* __restrict__ b1,
                            const float* __restrict__ W2, const float* __restrict__ b2,
                            const float* __restrict__ att, const float* __restrict__ bias,
                            float* __restrict__ lg, int B, int N) {
    __shared__ float W1s[D * CH], W2s[D * CH];
    int t = blockIdx.x;          // 0..B*NC-1
    int lane = threadIdx.x;      // 32 threads
    for (int i = lane; i < D * CH; i += 32) { W1s[i] = W1[i]; W2s[i] = W2[i]; }
    __syncwarp();

    int row = (t >> 3) * N + (t & 7);
    int k0 = lane * 4;

    float4 hr = *(const float4*)(h + (size_t)row * D + k0);
    float s2v[CH], attv[CH], b1v[CH];
    #pragma unroll
    for (int c = 0; c < CH; c++) {
        float p = hr.x * W2s[(k0 + 0) * CH + c] + hr.y * W2s[(k0 + 1) * CH + c]
                + hr.z * W2s[(k0 + 2) * CH + c] + hr.w * W2s[(k0 + 3) * CH + c];
        #pragma unroll
        for (int o = 16; o; o >>= 1) p += __shfl_xor_sync(0xffffffffu, p, o);
        s2v[c] = p + b2[c];
        attv[c] = att[c];
        b1v[c] = b1[c];
    }

    int beg = g_off[row], end = g_off[row + 1];
    float m = -INFINITY, d = 0.f;
    float acc[CH];
    #pragma unroll
    for (int c = 0; c < CH; c++) acc[c] = 0.f;

    for (int e = beg; e < end; e++) {
        int s = g_csr[e];
        float4 hs = *(const float4*)(h + (size_t)s * D + k0);
        float s1v[CH];
        #pragma unroll
        for (int c = 0; c < CH; c++) {
            float p = hs.x * W1s[(k0 + 0) * CH + c] + hs.y * W1s[(k0 + 1) * CH + c]
                    + hs.z * W1s[(k0 + 2) * CH + c] + hs.w * W1s[(k0 + 3) * CH + c];
            #pragma unroll
            for (int o = 16; o; o >>= 1) p += __shfl_xor_sync(0xffffffffu, p, o);
            s1v[c] = p + b1v[c];
        }
        float sc = 0.f;
        #pragma unroll
        for (int c = 0; c < CH; c++) {
            float tt = s1v[c] + s2v[c];
            tt = (tt > 0.f) ? tt : 0.2f * tt;
            sc = fmaf(tt, attv[c], sc);
        }
        if (sc <= m) {
            float wgt = __expf(sc - m);
            d += wgt;
            #pragma unroll
            for (int c = 0; c < CH; c++) acc[c] = fmaf(wgt, s1v[c], acc[c]);
        } else {
            float c1 = __expf(m - sc);
            d = d * c1 + 1.f;
            #pragma unroll
            for (int c = 0; c < CH; c++) acc[c] = acc[c] * c1 + s1v[c];
            m = sc;
        }
    }
    if (lane == 0) {
        float inv = 1.f / (d + 1e-16f);
        for (int c = 0; c < CH; c++)
            lg[t * CH + c] = acc[c] * inv + bias[c];
    }
}

// ---------------- actor head: softmax + gumbel + top-4 + sel -----------------
__global__ void k_actor(const float* __restrict__ logits, const float* __restrict__ gu,
                        float* __restrict__ out, int B, int N) {
    __shared__ float shp[4][NC][CH];
    int tid = threadIdx.x;            // 32 threads
    int b = tid >> 3, i = tid & 7;
    bool active = tid < B * NC;
    if (active) {
        float l[CH], mx = -INFINITY;
        for (int c = 0; c < CH; c++) { l[c] = logits[tid * CH + c]; mx = fmaxf(mx, l[c]); }
        float s = 0.f;
        for (int c = 0; c < CH; c++) { l[c] = expf(l[c] - mx); s += l[c]; }
        for (int c = 0; c < CH; c++) shp[b][i][c] = l[c] / s;
    }
    __syncthreads();
    if (active) {
        float sc[CH];
        for (int c = 0; c < CH; c++) {
            float u = gu[(b * NC + i) * CH + c];
            float g = -logf(-logf(u));
            sc[c] = logf(shp[b][i][c]) + g;
        }
        int base = (b * NC + i) * NS;
        int seloff = B * NC * NS;
        for (int j = 0; j < NS; j++) {
            int best = 0; float bv = -INFINITY;
            for (int c = 0; c < CH; c++)
                if (sc[c] > bv) { bv = sc[c]; best = c; }
            out[base + j] = (float)best;
            out[seloff + base + j] = shp[b][best][j];
            sc[best] = -INFINITY;
        }
    }
}

// ---------------- launch -----------------------------------------------------
extern "C" void kernel_launch(void* const* d_in, const int* in_sizes, int n_in,
                              void* d_out, int out_size) {
    const float* x  = (const float*)d_in[0];
    const int*   ei = (const int*)d_in[1];
    const float* gu = (const float*)d_in[2];
    const float* Wp[4][6];
    for (int l = 0; l < 4; l++)
        for (int j = 0; j < 6; j++)
            Wp[l][j] = (const float*)d_in[3 + l * 6 + j];
    const float* fcW = (const float*)d_in[27];
    const float* fcb = (const float*)d_in[28];

    int M = in_sizes[0] / D;
    int E = in_sizes[1] / 2;
    int B = in_sizes[2] / (NC * CH);
    int N = M / B;
    int ET = E + M;
    float* out = (float*)d_out;

    // one-time (first/correctness call, before graph capture) stream+event setup
    static cudaStream_t s1 = nullptr, s2 = nullptr, s3 = nullptr;
    static cudaEvent_t evA = nullptr, evB = nullptr, evG4 = nullptr,
                       evC0 = nullptr, evC1 = nullptr, evE = nullptr, evD = nullptr;
    if (!s1) {
        cudaStreamCreateWithFlags(&s1, cudaStreamNonBlocking);
        cudaStreamCreateWithFlags(&s2, cudaStreamNonBlocking);
        cudaStreamCreateWithFlags(&s3, cudaStreamNonBlocking);
        cudaEventCreateWithFlags(&evA, cudaEventDisableTiming);
        cudaEventCreateWithFlags(&evB, cudaEventDisableTiming);
        cudaEventCreateWithFlags(&evG4, cudaEventDisableTiming);
        cudaEventCreateWithFlags(&evC0, cudaEventDisableTiming);
        cudaEventCreateWithFlags(&evC1, cudaEventDisableTiming);
        cudaEventCreateWithFlags(&evE, cudaEventDisableTiming);
        cudaEventCreateWithFlags(&evD, cudaEventDisableTiming);
    }

    void *pc, *pwlc, *pxlA, *pxrA, *pxlC, *pxrC, *phA, *phC, *plg;
    cudaGetSymbolAddress(&pc,   g_count);
    cudaGetSymbolAddress(&pwlc, g_wlcount);
    cudaGetSymbolAddress(&pxlA, g_xlA);
    cudaGetSymbolAddress(&pxrA, g_xrA);
    cudaGetSymbolAddress(&pxlC, g_xlC);
    cudaGetSymbolAddress(&pxrC, g_xrC);
    cudaGetSymbolAddress(&phA,  g_hA);
    cudaGetSymbolAddress(&phC,  g_hC);
    cudaGetSymbolAddress(&plg,  g_lg);
    float* xlA = (float*)pxlA; float* xrA = (float*)pxrA;
    float* xlC = (float*)pxlC; float* xrC = (float*)pxrC;
    float* hA  = (float*)phA;  float* hC  = (float*)phC;
    float* lg  = (float*)plg;

    const int tb = 256;
    size_t smemN = (size_t)4 * 128 * LDB * sizeof(__nv_bfloat16);  // 139264
    cudaFuncSetAttribute(k_gemmN, cudaFuncAttributeMaxDynamicSharedMemorySize, (int)smemN);
    int gg  = (M + 127) / 128;
    int gE  = (ET + tb - 1) / tb; if (gE > 4096) gE = 4096;
    int gws = (M * 32 + tb - 1) / tb;

    int Mh = (((M + 1) / 2 + 127) / 128) * 128;   // chunk split, 128-aligned
    if (Mh > M) Mh = M;
    int ggh0 = (Mh + 127) / 128;
    int ggh1 = (M - Mh + 127) / 128;
    int gw0  = (Mh * 32 + tb - 1) / tb;
    int gw1  = ((M - Mh) * 32 + tb - 1) / tb;
    int gwB  = (M * 32 + tb - 1) / tb;
    int gwl  = (WLMAX * 32 + tb - 1) / tb;

    // ---- fork: CSR build (s1) || layer-1 GEMM (main) ----
    cudaEventRecord(evA, 0);
    cudaStreamWaitEvent(s1, evA, 0);

    cudaMemsetAsync(pc, 0, (size_t)(M + 1) * sizeof(int), s1);
    k_hist<<<gE, tb, 0, s1>>>(ei + E, E, M);
    k_scan<<<1, 1024, 0, s1>>>(M);
    k_scatter<<<gE, tb, 0, s1>>>(ei, ei + E, E, M);
    k_sortwarp<<<gws, tb, 0, s1>>>(M);
    cudaEventRecord(evB, s1);

    k_gemmN<<<gg, tb, smemN>>>(x, Wp[0][0], xlA, Wp[0][2], xrA,
                                  Wp[2][0], xlC, Wp[2][2], xrC, M, 4);
    cudaEventRecord(evG4, 0);

    // ---- actor branch (s3): worklist -> pruned gat -> head ----
    cudaStreamWaitEvent(s3, evB, 0);
    cudaStreamWaitEvent(s3, evG4, 0);
    cudaMemsetAsync(pwlc, 0, sizeof(int), s3);
    k_mkwl<<<1, 1024, 0, s3>>>(B, N);
    k_gat1wl<<<gwl, tb, 0, s3>>>(xlA, xrA, Wp[0][4], Wp[0][1], Wp[0][3], Wp[0][5],
                                 hA, 0.01f);
    k_actorhead<<<B * NC, 32, 0, s3>>>(hA, Wp[1][0], Wp[1][1], Wp[1][2], Wp[1][3],
                                       Wp[1][4], Wp[1][5], lg, B, N);
    k_actor<<<1, 32, 0, s3>>>(lg, gu, out, B, N);
    cudaEventRecord(evD, s3);

    // ---- critic: chunked gatC (main) pipelined with gemm2 (s2) ----
    cudaStreamWaitEvent(0, evB, 0);
    k_gat1<<<gw0, tb>>>(xlC, xrC, Wp[2][4], Wp[2][1], Wp[2][3], Wp[2][5],
                        hC, 0, Mh, 0.01f);
    cudaEventRecord(evC0, 0);
    if (M > Mh)
        k_gat1<<<gw1, tb>>>(xlC, xrC, Wp[2][4], Wp[2][1], Wp[2][3], Wp[2][5],
                            hC, Mh, M, 0.01f);
    cudaEventRecord(evC1, 0);

    cudaStreamWaitEvent(s2, evC0, 0);
    k_gemmN<<<ggh0, tb, smemN, s2>>>(hC, Wp[3][0], xlC, Wp[3][2], xrC,
                                         Wp[3][0], xlC, Wp[3][2], xrC, Mh, 2);
    cudaStreamWaitEvent(s2, evC1, 0);
    if (M > Mh)
        k_gemmN<<<ggh1, tb, smemN, s2>>>(hC + (size_t)Mh * D,
                                         Wp[3][0], xlC + (size_t)Mh * D,
                                         Wp[3][2], xrC + (size_t)Mh * D,
                                         Wp[3][0], xlC + (size_t)Mh * D,
                                         Wp[3][2], xrC + (size_t)Mh * D,
                                         M - Mh, 2);
    cudaEventRecord(evE, s2);

    // ---- gatV after full gemm2 ----
    cudaStreamWaitEvent(0, evE, 0);
    k_gatV<<<gwB, tb>>>(xlC, xrC, Wp[3][4], Wp[3][1], Wp[3][3], Wp[3][5],
                        fcW, fcb, out + 2 * B * NC * NS, M);

    // ---- final join ----
    cudaStreamWaitEvent(0, evD, 0);
}